// round 1
// baseline (speedup 1.0000x reference)
#include <cuda_runtime.h>

#define B_  2
#define S_  2048
#define D_  1024
#define H_  16
#define DK_ 64
#define M_  (B_ * S_)   // 4096 rows

// Scratch (allocation-free rule: device globals). 4 x 16 MB.
__device__ float g_q[M_ * D_];
__device__ float g_k[M_ * D_];
__device__ float g_v[M_ * D_];
__device__ float g_att[M_ * D_];

// ---------------------------------------------------------------------------
// Y[m][n] = sum_k X[m][k] * W[n][k]   (nn.Linear: y = x @ W^T)
// BM=BN=128, BK=16, 256 threads, 8x8 per thread (split 4+4 vectors).
// gridDim.z selects one of up to 3 (X, W, Y) triples (fused QKV projections).
// ---------------------------------------------------------------------------
__global__ __launch_bounds__(256) void sgemm_nt3(
    const float* __restrict__ X0, const float* __restrict__ W0, float* __restrict__ Y0,
    const float* __restrict__ X1, const float* __restrict__ W1, float* __restrict__ Y1,
    const float* __restrict__ X2, const float* __restrict__ W2, float* __restrict__ Y2,
    int M, int N, int K)
{
    const float* X; const float* W; float* Y;
    if (blockIdx.z == 0)      { X = X0; W = W0; Y = Y0; }
    else if (blockIdx.z == 1) { X = X1; W = W1; Y = Y1; }
    else                      { X = X2; W = W2; Y = Y2; }

    __shared__ float As[16][128];
    __shared__ float Bs[16][128];

    const int tid = threadIdx.x;
    const int tx = tid & 15;
    const int ty = tid >> 4;
    const int m0 = blockIdx.y * 128;
    const int n0 = blockIdx.x * 128;

    // global-load mapping: each thread loads 8 floats of A and 8 of B per k-tile
    const int lrow = tid >> 1;          // 0..127
    const int lk   = (tid & 1) * 8;     // 0 or 8
    const float* Xg = X + (size_t)(m0 + lrow) * K + lk;
    const float* Wg = W + (size_t)(n0 + lrow) * K + lk;

    float acc[8][8];
#pragma unroll
    for (int i = 0; i < 8; i++)
#pragma unroll
        for (int j = 0; j < 8; j++) acc[i][j] = 0.f;

    for (int k0 = 0; k0 < K; k0 += 16) {
        float4 xa = *(const float4*)(Xg + k0);
        float4 xb = *(const float4*)(Xg + k0 + 4);
        float4 wa = *(const float4*)(Wg + k0);
        float4 wb = *(const float4*)(Wg + k0 + 4);

        As[lk + 0][lrow] = xa.x; As[lk + 1][lrow] = xa.y;
        As[lk + 2][lrow] = xa.z; As[lk + 3][lrow] = xa.w;
        As[lk + 4][lrow] = xb.x; As[lk + 5][lrow] = xb.y;
        As[lk + 6][lrow] = xb.z; As[lk + 7][lrow] = xb.w;

        Bs[lk + 0][lrow] = wa.x; Bs[lk + 1][lrow] = wa.y;
        Bs[lk + 2][lrow] = wa.z; Bs[lk + 3][lrow] = wa.w;
        Bs[lk + 4][lrow] = wb.x; Bs[lk + 5][lrow] = wb.y;
        Bs[lk + 6][lrow] = wb.z; Bs[lk + 7][lrow] = wb.w;

        __syncthreads();

#pragma unroll
        for (int kk = 0; kk < 16; kk++) {
            float4 a0 = *(const float4*)&As[kk][ty * 4];
            float4 a1 = *(const float4*)&As[kk][64 + ty * 4];
            float4 b0 = *(const float4*)&Bs[kk][tx * 4];
            float4 b1 = *(const float4*)&Bs[kk][64 + tx * 4];
            float a[8] = {a0.x, a0.y, a0.z, a0.w, a1.x, a1.y, a1.z, a1.w};
            float b[8] = {b0.x, b0.y, b0.z, b0.w, b1.x, b1.y, b1.z, b1.w};
#pragma unroll
            for (int i = 0; i < 8; i++)
#pragma unroll
                for (int j = 0; j < 8; j++)
                    acc[i][j] += a[i] * b[j];
        }
        __syncthreads();
    }

#pragma unroll
    for (int i = 0; i < 8; i++) {
        int mi = m0 + ((i < 4) ? (ty * 4 + i) : (64 + ty * 4 + (i - 4)));
        float4 r0 = make_float4(acc[i][0], acc[i][1], acc[i][2], acc[i][3]);
        float4 r1 = make_float4(acc[i][4], acc[i][5], acc[i][6], acc[i][7]);
        *(float4*)(Y + (size_t)mi * N + n0 + tx * 4)      = r0;
        *(float4*)(Y + (size_t)mi * N + n0 + 64 + tx * 4) = r1;
    }
}

// ---------------------------------------------------------------------------
// Causal flash attention, fp32. One thread per query row, 128 queries/block.
// K/V staged in smem 64-key tiles; broadcast reads (conflict-free).
// Reads g_q/g_k/g_v (B,S,D layout with head h at columns h*64..h*64+63),
// writes concat output to g_att in the same layout.
// ---------------------------------------------------------------------------
__global__ __launch_bounds__(128) void attn_kernel()
{
    __shared__ float Ks[64][64];
    __shared__ float Vs[64][64];

    const int qt  = blockIdx.x;        // 0..15 query tile (128 rows)
    const int bh  = blockIdx.y;        // 0..31
    const int b   = bh >> 4;
    const int h   = bh & 15;
    const int tid = threadIdx.x;       // 128
    const int qg  = qt * 128 + tid;    // global query index within S

    const float* qbase = g_q + (size_t)(b * S_ + qg) * D_ + h * DK_;
    float4 q4[16];
#pragma unroll
    for (int i = 0; i < 16; i++) q4[i] = *(const float4*)(qbase + i * 4);

    float4 o4[16];
#pragma unroll
    for (int i = 0; i < 16; i++) o4[i] = make_float4(0.f, 0.f, 0.f, 0.f);
    float mmax = -1e30f;
    float lsum = 0.f;

    const int ntiles = 2 * qt + 2;     // 64-key tiles covering keys 0..qt*128+127
    for (int kt = 0; kt < ntiles; kt++) {
        const int kg0 = kt * 64;
        __syncthreads();               // prior tile's consumers done
#pragma unroll
        for (int it = 0; it < 8; it++) {
            int i   = tid + it * 128;          // 0..1023 float4 slots
            int row = i >> 4;
            int c   = (i & 15) * 4;
            size_t g = (size_t)(b * S_ + kg0 + row) * D_ + h * DK_ + c;
            *(float4*)&Ks[row][c] = *(const float4*)(g_k + g);
            *(float4*)&Vs[row][c] = *(const float4*)(g_v + g);
        }
        __syncthreads();

        const bool full = (kg0 + 63) <= qt * 128;
        const int jmax = full ? 64 : min(64, qg - kg0 + 1);   // may be <= 0

        for (int j = 0; j < jmax; j++) {
            float s0 = 0.f, s1 = 0.f, s2 = 0.f, s3 = 0.f;
#pragma unroll
            for (int i = 0; i < 16; i += 4) {
                float4 k0v = *(const float4*)&Ks[j][(i + 0) * 4];
                float4 k1v = *(const float4*)&Ks[j][(i + 1) * 4];
                float4 k2v = *(const float4*)&Ks[j][(i + 2) * 4];
                float4 k3v = *(const float4*)&Ks[j][(i + 3) * 4];
                s0 += q4[i + 0].x * k0v.x + q4[i + 0].y * k0v.y + q4[i + 0].z * k0v.z + q4[i + 0].w * k0v.w;
                s1 += q4[i + 1].x * k1v.x + q4[i + 1].y * k1v.y + q4[i + 1].z * k1v.z + q4[i + 1].w * k1v.w;
                s2 += q4[i + 2].x * k2v.x + q4[i + 2].y * k2v.y + q4[i + 2].z * k2v.z + q4[i + 2].w * k2v.w;
                s3 += q4[i + 3].x * k3v.x + q4[i + 3].y * k3v.y + q4[i + 3].z * k3v.z + q4[i + 3].w * k3v.w;
            }
            float s = ((s0 + s1) + (s2 + s3)) * 0.125f;   // / sqrt(64)

            if (s > mmax) {                                // rare after warmup
                float corr = __expf(mmax - s);
                lsum *= corr;
#pragma unroll
                for (int i = 0; i < 16; i++) {
                    o4[i].x *= corr; o4[i].y *= corr;
                    o4[i].z *= corr; o4[i].w *= corr;
                }
                mmax = s;
            }
            float p = __expf(s - mmax);
            lsum += p;
#pragma unroll
            for (int i = 0; i < 16; i++) {
                float4 vv = *(const float4*)&Vs[j][i * 4];
                o4[i].x += p * vv.x; o4[i].y += p * vv.y;
                o4[i].z += p * vv.z; o4[i].w += p * vv.w;
            }
        }
    }

    const float inv = 1.f / lsum;
    float* ob = g_att + (size_t)(b * S_ + qg) * D_ + h * DK_;
#pragma unroll
    for (int i = 0; i < 16; i++) {
        float4 r = make_float4(o4[i].x * inv, o4[i].y * inv, o4[i].z * inv, o4[i].w * inv);
        *(float4*)(ob + i * 4) = r;
    }
}

// ---------------------------------------------------------------------------
extern "C" void kernel_launch(void* const* d_in, const int* in_sizes, int n_in,
                              void* d_out, int out_size)
{
    (void)in_sizes; (void)n_in; (void)out_size;
    const float* q  = (const float*)d_in[0];
    const float* k  = (const float*)d_in[1];
    const float* v  = (const float*)d_in[2];
    // d_in[3] is the causal mask (int32) — causality is hardcoded.
    const float* Wq = (const float*)d_in[4];
    const float* Wk = (const float*)d_in[5];
    const float* Wv = (const float*)d_in[6];
    const float* Wo = (const float*)d_in[7];
    float* out = (float*)d_out;

    float *gq, *gk, *gv, *gatt;
    cudaGetSymbolAddress((void**)&gq,   g_q);
    cudaGetSymbolAddress((void**)&gk,   g_k);
    cudaGetSymbolAddress((void**)&gv,   g_v);
    cudaGetSymbolAddress((void**)&gatt, g_att);

    // 1) Fused QKV projections: 3 GEMMs in one grid (z selects operand set).
    dim3 gproj(D_ / 128, M_ / 128, 3);   // (8, 32, 3) = 768 blocks
    sgemm_nt3<<<gproj, 256>>>(q, Wq, gq,
                              k, Wk, gk,
                              v, Wv, gv,
                              M_, D_, D_);

    // 2) Causal flash attention -> concat layout in g_att.
    dim3 gattn(S_ / 128, B_ * H_);       // (16, 32)
    attn_kernel<<<gattn, 128>>>();

    // 3) Output projection: d_out = g_att @ Wo^T.
    dim3 gout(D_ / 128, M_ / 128, 1);
    sgemm_nt3<<<gout, 256>>>(gatt, Wo, out,
                             gatt, Wo, out,
                             gatt, Wo, out,
                             M_, D_, D_);
}

// round 3
// speedup vs baseline: 1.4217x; 1.4217x over previous
#include <cuda_runtime.h>
#include <cuda_bf16.h>
#include <cstdint>

#define B_  2
#define S_  2048
#define D_  1024
#define H_  16
#define DK_ 64
#define M_  (B_ * S_)   // 4096

// ---------------------------------------------------------------------------
// Scratch (allocation-free rule: device globals)
// ---------------------------------------------------------------------------
__device__ float g_q[M_ * D_];
__device__ float g_k[M_ * D_];
__device__ float g_v[M_ * D_];
__device__ float g_att[M_ * D_];

__device__ __nv_bfloat16 g_qh[M_ * D_], g_ql[M_ * D_];
__device__ __nv_bfloat16 g_kh[M_ * D_], g_kl[M_ * D_];
__device__ __nv_bfloat16 g_vh[M_ * D_], g_vl[M_ * D_];
__device__ __nv_bfloat16 g_ah[M_ * D_], g_al[M_ * D_];
__device__ __nv_bfloat16 g_wqh[D_ * D_], g_wql[D_ * D_];
__device__ __nv_bfloat16 g_wkh[D_ * D_], g_wkl[D_ * D_];
__device__ __nv_bfloat16 g_wvh[D_ * D_], g_wvl[D_ * D_];
__device__ __nv_bfloat16 g_woh[D_ * D_], g_wol[D_ * D_];

// ---------------------------------------------------------------------------
__device__ __forceinline__ uint32_t smem_u32(const void* p) {
    uint32_t a;
    asm("{ .reg .u64 t; cvta.to.shared.u64 t, %1; cvt.u32.u64 %0, t; }" : "=r"(a) : "l"(p));
    return a;
}
// byte offset within a 128rows x 32cols bf16 tile, 2 rows packed per 128B line,
// then SW128 XOR swizzle (conflict-free for ldmatrix 8-row reads; proven pattern).
__device__ __forceinline__ uint32_t tile_off(int row, int k) {
    uint32_t b = ((uint32_t)(row >> 1) << 7) | ((uint32_t)(row & 1) << 6) | ((uint32_t)k << 1);
    return b ^ ((b >> 3) & 0x70);
}
__device__ __forceinline__ void ldsm_x4(uint32_t* r, uint32_t addr) {
    asm volatile("ldmatrix.sync.aligned.m8n8.x4.shared.b16 {%0,%1,%2,%3}, [%4];"
                 : "=r"(r[0]), "=r"(r[1]), "=r"(r[2]), "=r"(r[3]) : "r"(addr));
}
__device__ __forceinline__ void mma_16816(float* c, const uint32_t* a, uint32_t b0, uint32_t b1) {
    asm volatile("mma.sync.aligned.m16n8k16.row.col.f32.bf16.bf16.f32 "
                 "{%0,%1,%2,%3}, {%4,%5,%6,%7}, {%8,%9}, {%0,%1,%2,%3};"
                 : "+f"(c[0]), "+f"(c[1]), "+f"(c[2]), "+f"(c[3])
                 : "r"(a[0]), "r"(a[1]), "r"(a[2]), "r"(a[3]), "r"(b0), "r"(b1));
}
__device__ __forceinline__ void cp_async16(uint32_t saddr, const void* gaddr) {
    asm volatile("cp.async.cg.shared.global [%0], [%1], 16;" :: "r"(saddr), "l"(gaddr));
}
#define CP_COMMIT()  asm volatile("cp.async.commit_group;" ::: "memory")
#define CP_WAIT(n)   asm volatile("cp.async.wait_group %0;" :: "n"(n) : "memory")

// ---------------------------------------------------------------------------
// fp32 -> (bf16 hi, bf16 lo) split
// ---------------------------------------------------------------------------
__global__ __launch_bounds__(256) void split_kernel(const float* __restrict__ src,
                                                    __nv_bfloat16* __restrict__ hi,
                                                    __nv_bfloat16* __restrict__ lo, int n4)
{
    int idx = blockIdx.x * 256 + threadIdx.x;
    if (idx >= n4) return;
    float4 x = ((const float4*)src)[idx];
    __nv_bfloat16 h0 = __float2bfloat16(x.x);
    __nv_bfloat16 h1 = __float2bfloat16(x.y);
    __nv_bfloat16 h2 = __float2bfloat16(x.z);
    __nv_bfloat16 h3 = __float2bfloat16(x.w);
    __nv_bfloat16 l0 = __float2bfloat16(x.x - __bfloat162float(h0));
    __nv_bfloat16 l1 = __float2bfloat16(x.y - __bfloat162float(h1));
    __nv_bfloat16 l2 = __float2bfloat16(x.z - __bfloat162float(h2));
    __nv_bfloat16 l3 = __float2bfloat16(x.w - __bfloat162float(h3));
    __nv_bfloat162 hv0 = __nv_bfloat162(h0, h1), hv1 = __nv_bfloat162(h2, h3);
    __nv_bfloat162 lv0 = __nv_bfloat162(l0, l1), lv1 = __nv_bfloat162(l2, l3);
    ((uint2*)hi)[idx] = make_uint2(*(uint32_t*)&hv0, *(uint32_t*)&hv1);
    ((uint2*)lo)[idx] = make_uint2(*(uint32_t*)&lv0, *(uint32_t*)&lv1);
}

// ---------------------------------------------------------------------------
// HMMA GEMM: Y[M,N] = X[M,K] @ W[N,K]^T, bf16x3 split (hh + hl + lh), fp32 acc.
// 128x128 CTA tile, BK=32, 8 warps (2m x 4n), warp tile 64x32.
// cp.async double-buffered smem. gridDim.z picks operand set.
// ---------------------------------------------------------------------------
#define TILE_B 8192                  // one 128x32 bf16 tile (swizzled)
#define NITER  96                    // 3 passes * 32 k-chunks

__global__ __launch_bounds__(256) void hmma_gemm3(
    const __nv_bfloat16* __restrict__ Xh0, const __nv_bfloat16* __restrict__ Xl0,
    const __nv_bfloat16* __restrict__ Wh0, const __nv_bfloat16* __restrict__ Wl0, float* __restrict__ Y0,
    const __nv_bfloat16* __restrict__ Xh1, const __nv_bfloat16* __restrict__ Xl1,
    const __nv_bfloat16* __restrict__ Wh1, const __nv_bfloat16* __restrict__ Wl1, float* __restrict__ Y1,
    const __nv_bfloat16* __restrict__ Xh2, const __nv_bfloat16* __restrict__ Xl2,
    const __nv_bfloat16* __restrict__ Wh2, const __nv_bfloat16* __restrict__ Wl2, float* __restrict__ Y2)
{
    const __nv_bfloat16 *Xh, *Xl, *Wh, *Wl; float* Y;
    if (blockIdx.z == 0)      { Xh = Xh0; Xl = Xl0; Wh = Wh0; Wl = Wl0; Y = Y0; }
    else if (blockIdx.z == 1) { Xh = Xh1; Xl = Xl1; Wh = Wh1; Wl = Wl1; Y = Y1; }
    else                      { Xh = Xh2; Xl = Xl2; Wh = Wh2; Wl = Wl2; Y = Y2; }

    __shared__ char smem[4 * TILE_B];          // A0 B0 A1 B1
    const uint32_t sb = smem_u32(smem);

    const int tid = threadIdx.x;
    const int wid = tid >> 5;
    const int lid = tid & 31;
    const int m0 = blockIdx.y * 128;
    const int n0 = blockIdx.x * 128;
    const int wr = (wid & 1) * 64;             // warp m offset in tile
    const int wn = (wid >> 1) * 32;            // warp n offset in tile

    // --- global->smem mapping: thread t moves 2x16B of A and 2x16B of B ---
    const int r0 = tid >> 2;                   // 0..63
    const int kb = (tid & 3) * 8;              // k element offset of 16B unit
    const uint32_t so0 = tile_off(r0, kb);
    const uint32_t so1 = tile_off(r0 + 64, kb);
    const size_t go0 = (size_t)r0 * D_ + kb;
    const size_t go1 = (size_t)(r0 + 64) * D_ + kb;

    // --- ldmatrix per-lane offsets (within a tile) ---
    const int sub = lid >> 3, l7 = lid & 7;
    uint32_t offA[2][4], offB[2][2];
#pragma unroll
    for (int ks = 0; ks < 2; ks++) {
#pragma unroll
        for (int i = 0; i < 4; i++)
            offA[ks][i] = tile_off(wr + i * 16 + (sub & 1) * 8 + l7, ks * 16 + (sub >> 1) * 8);
#pragma unroll
        for (int j = 0; j < 2; j++)
            offB[ks][j] = tile_off(wn + j * 16 + (sub >> 1) * 8 + l7, ks * 16 + (sub & 1) * 8);
    }

    float acc[4][4][4];
#pragma unroll
    for (int i = 0; i < 4; i++)
#pragma unroll
        for (int j = 0; j < 4; j++)
#pragma unroll
            for (int c = 0; c < 4; c++) acc[i][j][c] = 0.f;

    // issue one iteration's async copies
    auto issue = [&](int it) {
        const int pass = it >> 5;
        const int k0 = (it & 31) * 32;
        const uint32_t bufb = sb + (uint32_t)(it & 1) * (2 * TILE_B);
        const __nv_bfloat16* Ag = (pass == 2) ? Xl : Xh;
        const __nv_bfloat16* Bg = (pass == 1) ? Wl : Wh;
        const __nv_bfloat16* Ab = Ag + (size_t)m0 * D_ + k0;
        const __nv_bfloat16* Bb = Bg + (size_t)n0 * D_ + k0;
        cp_async16(bufb + so0,          Ab + go0);
        cp_async16(bufb + so1,          Ab + go1);
        cp_async16(bufb + TILE_B + so0, Bb + go0);
        cp_async16(bufb + TILE_B + so1, Bb + go1);
    };

    issue(0); CP_COMMIT();

    for (int it = 0; it < NITER; it++) {
        if (it + 1 < NITER) { issue(it + 1); CP_COMMIT(); CP_WAIT(1); }
        else                { CP_WAIT(0); }
        __syncthreads();

        const uint32_t sA = sb + (uint32_t)(it & 1) * (2 * TILE_B);
        const uint32_t sB = sA + TILE_B;
#pragma unroll
        for (int ks = 0; ks < 2; ks++) {
            uint32_t a[4][4], b[2][4];
#pragma unroll
            for (int i = 0; i < 4; i++) ldsm_x4(a[i], sA + offA[ks][i]);
#pragma unroll
            for (int j = 0; j < 2; j++) ldsm_x4(b[j], sB + offB[ks][j]);
#pragma unroll
            for (int i = 0; i < 4; i++) {
#pragma unroll
                for (int jj = 0; jj < 4; jj++) {
                    uint32_t b0 = b[jj >> 1][(jj & 1) * 2];
                    uint32_t b1 = b[jj >> 1][(jj & 1) * 2 + 1];
                    mma_16816(acc[i][jj], a[i], b0, b1);
                }
            }
        }
        __syncthreads();
    }

    // epilogue: fp32 stores, mma C layout (row = l>>2 / +8, col = (l&3)*2, +1)
    const int er = lid >> 2;
    const int ec = (lid & 3) * 2;
#pragma unroll
    for (int i = 0; i < 4; i++) {
#pragma unroll
        for (int jj = 0; jj < 4; jj++) {
            int row = m0 + wr + i * 16 + er;
            int col = n0 + wn + jj * 8 + ec;
            *(float2*)(Y + (size_t)row * D_ + col)       = make_float2(acc[i][jj][0], acc[i][jj][1]);
            *(float2*)(Y + (size_t)(row + 8) * D_ + col) = make_float2(acc[i][jj][2], acc[i][jj][3]);
        }
    }
}

// ---------------------------------------------------------------------------
// Causal flash attention, fp32 (unchanged).
// ---------------------------------------------------------------------------
__global__ __launch_bounds__(128) void attn_kernel()
{
    __shared__ float Ks[64][64];
    __shared__ float Vs[64][64];

    const int qt  = blockIdx.x;
    const int bh  = blockIdx.y;
    const int b   = bh >> 4;
    const int h   = bh & 15;
    const int tid = threadIdx.x;
    const int qg  = qt * 128 + tid;

    const float* qbase = g_q + (size_t)(b * S_ + qg) * D_ + h * DK_;
    float4 q4[16];
#pragma unroll
    for (int i = 0; i < 16; i++) q4[i] = *(const float4*)(qbase + i * 4);

    float4 o4[16];
#pragma unroll
    for (int i = 0; i < 16; i++) o4[i] = make_float4(0.f, 0.f, 0.f, 0.f);
    float mmax = -1e30f;
    float lsum = 0.f;

    const int ntiles = 2 * qt + 2;
    for (int kt = 0; kt < ntiles; kt++) {
        const int kg0 = kt * 64;
        __syncthreads();
#pragma unroll
        for (int it = 0; it < 8; it++) {
            int i   = tid + it * 128;
            int row = i >> 4;
            int c   = (i & 15) * 4;
            size_t g = (size_t)(b * S_ + kg0 + row) * D_ + h * DK_ + c;
            *(float4*)&Ks[row][c] = *(const float4*)(g_k + g);
            *(float4*)&Vs[row][c] = *(const float4*)(g_v + g);
        }
        __syncthreads();

        const bool full = (kg0 + 63) <= qt * 128;
        const int jmax = full ? 64 : min(64, qg - kg0 + 1);

        for (int j = 0; j < jmax; j++) {
            float s0 = 0.f, s1 = 0.f, s2 = 0.f, s3 = 0.f;
#pragma unroll
            for (int i = 0; i < 16; i += 4) {
                float4 k0v = *(const float4*)&Ks[j][(i + 0) * 4];
                float4 k1v = *(const float4*)&Ks[j][(i + 1) * 4];
                float4 k2v = *(const float4*)&Ks[j][(i + 2) * 4];
                float4 k3v = *(const float4*)&Ks[j][(i + 3) * 4];
                s0 += q4[i + 0].x * k0v.x + q4[i + 0].y * k0v.y + q4[i + 0].z * k0v.z + q4[i + 0].w * k0v.w;
                s1 += q4[i + 1].x * k1v.x + q4[i + 1].y * k1v.y + q4[i + 1].z * k1v.z + q4[i + 1].w * k1v.w;
                s2 += q4[i + 2].x * k2v.x + q4[i + 2].y * k2v.y + q4[i + 2].z * k2v.z + q4[i + 2].w * k2v.w;
                s3 += q4[i + 3].x * k3v.x + q4[i + 3].y * k3v.y + q4[i + 3].z * k3v.z + q4[i + 3].w * k3v.w;
            }
            float s = ((s0 + s1) + (s2 + s3)) * 0.125f;

            if (s > mmax) {
                float corr = __expf(mmax - s);
                lsum *= corr;
#pragma unroll
                for (int i = 0; i < 16; i++) {
                    o4[i].x *= corr; o4[i].y *= corr;
                    o4[i].z *= corr; o4[i].w *= corr;
                }
                mmax = s;
            }
            float p = __expf(s - mmax);
            lsum += p;
#pragma unroll
            for (int i = 0; i < 16; i++) {
                float4 vv = *(const float4*)&Vs[j][i * 4];
                o4[i].x += p * vv.x; o4[i].y += p * vv.y;
                o4[i].z += p * vv.z; o4[i].w += p * vv.w;
            }
        }
    }

    const float inv = 1.f / lsum;
    float* ob = g_att + (size_t)(b * S_ + qg) * D_ + h * DK_;
#pragma unroll
    for (int i = 0; i < 16; i++) {
        float4 r = make_float4(o4[i].x * inv, o4[i].y * inv, o4[i].z * inv, o4[i].w * inv);
        *(float4*)(ob + i * 4) = r;
    }
}

// ---------------------------------------------------------------------------
extern "C" void kernel_launch(void* const* d_in, const int* in_sizes, int n_in,
                              void* d_out, int out_size)
{
    (void)in_sizes; (void)n_in; (void)out_size;
    const float* q  = (const float*)d_in[0];
    const float* k  = (const float*)d_in[1];
    const float* v  = (const float*)d_in[2];
    const float* Wq = (const float*)d_in[4];
    const float* Wk = (const float*)d_in[5];
    const float* Wv = (const float*)d_in[6];
    const float* Wo = (const float*)d_in[7];
    float* out = (float*)d_out;

    float *gq, *gk, *gv, *gatt;
    cudaGetSymbolAddress((void**)&gq,   g_q);
    cudaGetSymbolAddress((void**)&gk,   g_k);
    cudaGetSymbolAddress((void**)&gv,   g_v);
    cudaGetSymbolAddress((void**)&gatt, g_att);

    __nv_bfloat16 *qh, *ql, *kh, *kl, *vh, *vl, *ah, *al;
    __nv_bfloat16 *wqh, *wql, *wkh, *wkl, *wvh, *wvl, *woh, *wol;
    cudaGetSymbolAddress((void**)&qh, g_qh);  cudaGetSymbolAddress((void**)&ql, g_ql);
    cudaGetSymbolAddress((void**)&kh, g_kh);  cudaGetSymbolAddress((void**)&kl, g_kl);
    cudaGetSymbolAddress((void**)&vh, g_vh);  cudaGetSymbolAddress((void**)&vl, g_vl);
    cudaGetSymbolAddress((void**)&ah, g_ah);  cudaGetSymbolAddress((void**)&al, g_al);
    cudaGetSymbolAddress((void**)&wqh, g_wqh); cudaGetSymbolAddress((void**)&wql, g_wql);
    cudaGetSymbolAddress((void**)&wkh, g_wkh); cudaGetSymbolAddress((void**)&wkl, g_wkl);
    cudaGetSymbolAddress((void**)&wvh, g_wvh); cudaGetSymbolAddress((void**)&wvl, g_wvl);
    cudaGetSymbolAddress((void**)&woh, g_woh); cudaGetSymbolAddress((void**)&wol, g_wol);

    const int n4_big = (M_ * D_) / 4;
    const int n4_w   = (D_ * D_) / 4;

    // 1) split GEMM inputs
    split_kernel<<<n4_big / 256, 256>>>(q, qh, ql, n4_big);
    split_kernel<<<n4_big / 256, 256>>>(k, kh, kl, n4_big);
    split_kernel<<<n4_big / 256, 256>>>(v, vh, vl, n4_big);
    split_kernel<<<n4_w / 256, 256>>>(Wq, wqh, wql, n4_w);
    split_kernel<<<n4_w / 256, 256>>>(Wk, wkh, wkl, n4_w);
    split_kernel<<<n4_w / 256, 256>>>(Wv, wvh, wvl, n4_w);
    split_kernel<<<n4_w / 256, 256>>>(Wo, woh, wol, n4_w);

    // 2) QKV projections on tensor cores
    dim3 gproj(D_ / 128, M_ / 128, 3);
    hmma_gemm3<<<gproj, 256>>>(
        qh, ql, wqh, wql, gq,
        kh, kl, wkh, wkl, gk,
        vh, vl, wvh, wvl, gv);

    // 3) causal flash attention (fp32)
    dim3 gattn(S_ / 128, B_ * H_);
    attn_kernel<<<gattn, 128>>>();

    // 4) split attention output, output projection on tensor cores
    split_kernel<<<n4_big / 256, 256>>>(gatt, ah, al, n4_big);
    dim3 gout(D_ / 128, M_ / 128, 1);
    hmma_gemm3<<<gout, 256>>>(
        ah, al, woh, wol, out,
        ah, al, woh, wol, out,
        ah, al, woh, wol, out);
}

// round 4
// speedup vs baseline: 3.1356x; 2.2056x over previous
#include <cuda_runtime.h>
#include <cuda_bf16.h>
#include <cstdint>

#define B_  2
#define S_  2048
#define D_  1024
#define H_  16
#define DK_ 64
#define M_  (B_ * S_)   // 4096

// ---------------------------------------------------------------------------
// Scratch (allocation-free rule: device globals), all bf16 hi/lo pairs
// ---------------------------------------------------------------------------
// input splits (A operands of QKV GEMMs)
__device__ __nv_bfloat16 g_xqh[M_ * D_], g_xql[M_ * D_];
__device__ __nv_bfloat16 g_xkh[M_ * D_], g_xkl[M_ * D_];
__device__ __nv_bfloat16 g_xvh[M_ * D_], g_xvl[M_ * D_];
// weight splits
__device__ __nv_bfloat16 g_wqh[D_ * D_], g_wql[D_ * D_];
__device__ __nv_bfloat16 g_wkh[D_ * D_], g_wkl[D_ * D_];
__device__ __nv_bfloat16 g_wvh[D_ * D_], g_wvl[D_ * D_];
__device__ __nv_bfloat16 g_woh[D_ * D_], g_wol[D_ * D_];
// projected Q/K/V splits (GEMM outputs)
__device__ __nv_bfloat16 g_qh[M_ * D_], g_ql[M_ * D_];
__device__ __nv_bfloat16 g_kh[M_ * D_], g_kl[M_ * D_];
__device__ __nv_bfloat16 g_vh[M_ * D_], g_vl[M_ * D_];
// attention output splits (out-proj A operand)
__device__ __nv_bfloat16 g_ah[M_ * D_], g_al[M_ * D_];

// ---------------------------------------------------------------------------
__device__ __forceinline__ uint32_t smem_u32(const void* p) {
    uint32_t a;
    asm("{ .reg .u64 t; cvta.to.shared.u64 t, %1; cvt.u32.u64 %0, t; }" : "=r"(a) : "l"(p));
    return a;
}
__device__ __forceinline__ void ldsm_x4(uint32_t* r, uint32_t addr) {
    asm volatile("ldmatrix.sync.aligned.m8n8.x4.shared.b16 {%0,%1,%2,%3}, [%4];"
                 : "=r"(r[0]), "=r"(r[1]), "=r"(r[2]), "=r"(r[3]) : "r"(addr));
}
__device__ __forceinline__ void ldsm_x4_t(uint32_t* r, uint32_t addr) {
    asm volatile("ldmatrix.sync.aligned.m8n8.x4.trans.shared.b16 {%0,%1,%2,%3}, [%4];"
                 : "=r"(r[0]), "=r"(r[1]), "=r"(r[2]), "=r"(r[3]) : "r"(addr));
}
__device__ __forceinline__ void mma_16816(float* c, const uint32_t* a, uint32_t b0, uint32_t b1) {
    asm volatile("mma.sync.aligned.m16n8k16.row.col.f32.bf16.bf16.f32 "
                 "{%0,%1,%2,%3}, {%4,%5,%6,%7}, {%8,%9}, {%0,%1,%2,%3};"
                 : "+f"(c[0]), "+f"(c[1]), "+f"(c[2]), "+f"(c[3])
                 : "r"(a[0]), "r"(a[1]), "r"(a[2]), "r"(a[3]), "r"(b0), "r"(b1));
}
__device__ __forceinline__ void cp_async16(uint32_t saddr, const void* gaddr) {
    asm volatile("cp.async.cg.shared.global [%0], [%1], 16;" :: "r"(saddr), "l"(gaddr));
}
#define CP_COMMIT()  asm volatile("cp.async.commit_group;" ::: "memory")
#define CP_WAIT(n)   asm volatile("cp.async.wait_group %0;" :: "n"(n) : "memory")
#define SWZ(off) ((off) ^ (((off) >> 3) & 0x70))

// pack two floats to bf16x2: low half = f0, high half = f1
__device__ __forceinline__ uint32_t pack_bf16x2(float f0, float f1) {
    uint32_t r;
    asm("cvt.rn.bf16x2.f32 %0, %1, %2;" : "=r"(r) : "f"(f1), "f"(f0));
    return r;
}
__device__ __forceinline__ float bf16lo_f(uint32_t p) { return __uint_as_float(p << 16); }
__device__ __forceinline__ float bf16hi_f(uint32_t p) { return __uint_as_float(p & 0xffff0000u); }

// FFMA-pipe 2^x (x <= ~0 expected; clamped below; rel err ~2e-6)
__device__ __forceinline__ float fexp2(float x) {
    x = fmaxf(x, -126.0f);
    float r = rintf(x);
    float f = x - r;
    float p = 1.3333558e-3f;
    p = fmaf(p, f, 9.6181291e-3f);
    p = fmaf(p, f, 5.5504109e-2f);
    p = fmaf(p, f, 2.4022651e-1f);
    p = fmaf(p, f, 6.9314718e-1f);
    p = fmaf(p, f, 1.0f);
    return p * __int_as_float(((int)r + 127) << 23);
}
#define LOG2E 1.4426950408889634f
#define SCALE_C (0.125f * LOG2E)     // fold 1/sqrt(64) and log2(e)

// ---------------------------------------------------------------------------
// fp32 -> (bf16 hi, bf16 lo) split
// ---------------------------------------------------------------------------
__global__ __launch_bounds__(256) void split_kernel(const float* __restrict__ src,
                                                    __nv_bfloat16* __restrict__ hi,
                                                    __nv_bfloat16* __restrict__ lo, int n4)
{
    int idx = blockIdx.x * 256 + threadIdx.x;
    if (idx >= n4) return;
    float4 x = ((const float4*)src)[idx];
    uint32_t h0 = pack_bf16x2(x.x, x.y);
    uint32_t h1 = pack_bf16x2(x.z, x.w);
    uint32_t l0 = pack_bf16x2(x.x - bf16lo_f(h0), x.y - bf16hi_f(h0));
    uint32_t l1 = pack_bf16x2(x.z - bf16lo_f(h1), x.w - bf16hi_f(h1));
    ((uint2*)hi)[idx] = make_uint2(h0, h1);
    ((uint2*)lo)[idx] = make_uint2(l0, l1);
}

// ---------------------------------------------------------------------------
// HMMA GEMM: Y = X @ W^T, bf16x3 split, fp32 acc. 128x128 CTA, BK=32, 8 warps.
// Output: fp32 (Yf) or bf16 hi/lo split (Yh/Yl) when Yh != nullptr.
// ---------------------------------------------------------------------------
#define TILE_B 8192
#define NITER  96
// packed 128x32 bf16 tile offset (2 rows per 128B line + SW128)
__device__ __forceinline__ uint32_t tile_off(int row, int k) {
    uint32_t b = ((uint32_t)(row >> 1) << 7) | ((uint32_t)(row & 1) << 6) | ((uint32_t)k << 1);
    return SWZ(b);
}

__global__ __launch_bounds__(256) void hmma_gemm3(
    const __nv_bfloat16* __restrict__ Xh0, const __nv_bfloat16* __restrict__ Xl0,
    const __nv_bfloat16* __restrict__ Wh0, const __nv_bfloat16* __restrict__ Wl0,
    float* Yf0, __nv_bfloat16* Yh0, __nv_bfloat16* Yl0,
    const __nv_bfloat16* __restrict__ Xh1, const __nv_bfloat16* __restrict__ Xl1,
    const __nv_bfloat16* __restrict__ Wh1, const __nv_bfloat16* __restrict__ Wl1,
    float* Yf1, __nv_bfloat16* Yh1, __nv_bfloat16* Yl1,
    const __nv_bfloat16* __restrict__ Xh2, const __nv_bfloat16* __restrict__ Xl2,
    const __nv_bfloat16* __restrict__ Wh2, const __nv_bfloat16* __restrict__ Wl2,
    float* Yf2, __nv_bfloat16* Yh2, __nv_bfloat16* Yl2)
{
    const __nv_bfloat16 *Xh, *Xl, *Wh, *Wl; float* Yf; __nv_bfloat16 *Yh, *Yl;
    if (blockIdx.z == 0)      { Xh=Xh0; Xl=Xl0; Wh=Wh0; Wl=Wl0; Yf=Yf0; Yh=Yh0; Yl=Yl0; }
    else if (blockIdx.z == 1) { Xh=Xh1; Xl=Xl1; Wh=Wh1; Wl=Wl1; Yf=Yf1; Yh=Yh1; Yl=Yl1; }
    else                      { Xh=Xh2; Xl=Xl2; Wh=Wh2; Wl=Wl2; Yf=Yf2; Yh=Yh2; Yl=Yl2; }

    __shared__ char smem[4 * TILE_B];
    const uint32_t sb = smem_u32(smem);

    const int tid = threadIdx.x;
    const int wid = tid >> 5;
    const int lid = tid & 31;
    const int m0 = blockIdx.y * 128;
    const int n0 = blockIdx.x * 128;
    const int wr = (wid & 1) * 64;
    const int wn = (wid >> 1) * 32;

    const int r0 = tid >> 2;
    const int kb = (tid & 3) * 8;
    const uint32_t so0 = tile_off(r0, kb);
    const uint32_t so1 = tile_off(r0 + 64, kb);
    const size_t go0 = (size_t)r0 * D_ + kb;
    const size_t go1 = (size_t)(r0 + 64) * D_ + kb;

    const int sub = lid >> 3, l7 = lid & 7;
    uint32_t offA[2][4], offB[2][2];
#pragma unroll
    for (int ks = 0; ks < 2; ks++) {
#pragma unroll
        for (int i = 0; i < 4; i++)
            offA[ks][i] = tile_off(wr + i * 16 + (sub & 1) * 8 + l7, ks * 16 + (sub >> 1) * 8);
#pragma unroll
        for (int j = 0; j < 2; j++)
            offB[ks][j] = tile_off(wn + j * 16 + (sub >> 1) * 8 + l7, ks * 16 + (sub & 1) * 8);
    }

    float acc[4][4][4];
#pragma unroll
    for (int i = 0; i < 4; i++)
#pragma unroll
        for (int j = 0; j < 4; j++)
#pragma unroll
            for (int c = 0; c < 4; c++) acc[i][j][c] = 0.f;

    auto issue = [&](int it) {
        const int pass = it >> 5;
        const int k0 = (it & 31) * 32;
        const uint32_t bufb = sb + (uint32_t)(it & 1) * (2 * TILE_B);
        const __nv_bfloat16* Ag = (pass == 2) ? Xl : Xh;
        const __nv_bfloat16* Bg = (pass == 1) ? Wl : Wh;
        const __nv_bfloat16* Ab = Ag + (size_t)m0 * D_ + k0;
        const __nv_bfloat16* Bb = Bg + (size_t)n0 * D_ + k0;
        cp_async16(bufb + so0,          Ab + go0);
        cp_async16(bufb + so1,          Ab + go1);
        cp_async16(bufb + TILE_B + so0, Bb + go0);
        cp_async16(bufb + TILE_B + so1, Bb + go1);
    };

    issue(0); CP_COMMIT();

    for (int it = 0; it < NITER; it++) {
        if (it + 1 < NITER) { issue(it + 1); CP_COMMIT(); CP_WAIT(1); }
        else                { CP_WAIT(0); }
        __syncthreads();

        const uint32_t sA = sb + (uint32_t)(it & 1) * (2 * TILE_B);
        const uint32_t sB = sA + TILE_B;
#pragma unroll
        for (int ks = 0; ks < 2; ks++) {
            uint32_t a[4][4], b[2][4];
#pragma unroll
            for (int i = 0; i < 4; i++) ldsm_x4(a[i], sA + offA[ks][i]);
#pragma unroll
            for (int j = 0; j < 2; j++) ldsm_x4(b[j], sB + offB[ks][j]);
#pragma unroll
            for (int i = 0; i < 4; i++)
#pragma unroll
                for (int jj = 0; jj < 4; jj++)
                    mma_16816(acc[i][jj], a[i], b[jj >> 1][(jj & 1) * 2], b[jj >> 1][(jj & 1) * 2 + 1]);
        }
        __syncthreads();
    }

    const int er = lid >> 2;
    const int ec = (lid & 3) * 2;
    if (Yh) {
#pragma unroll
        for (int i = 0; i < 4; i++)
#pragma unroll
            for (int jj = 0; jj < 4; jj++) {
                size_t p0 = (size_t)(m0 + wr + i * 16 + er) * D_ + n0 + wn + jj * 8 + ec;
                size_t p1 = p0 + 8 * (size_t)D_;
                float* a4 = acc[i][jj];
                uint32_t h0 = pack_bf16x2(a4[0], a4[1]);
                uint32_t h1 = pack_bf16x2(a4[2], a4[3]);
                uint32_t l0 = pack_bf16x2(a4[0] - bf16lo_f(h0), a4[1] - bf16hi_f(h0));
                uint32_t l1 = pack_bf16x2(a4[2] - bf16lo_f(h1), a4[3] - bf16hi_f(h1));
                *(uint32_t*)(Yh + p0) = h0; *(uint32_t*)(Yl + p0) = l0;
                *(uint32_t*)(Yh + p1) = h1; *(uint32_t*)(Yl + p1) = l1;
            }
    } else {
#pragma unroll
        for (int i = 0; i < 4; i++)
#pragma unroll
            for (int jj = 0; jj < 4; jj++) {
                size_t p0 = (size_t)(m0 + wr + i * 16 + er) * D_ + n0 + wn + jj * 8 + ec;
                *(float2*)(Yf + p0)               = make_float2(acc[i][jj][0], acc[i][jj][1]);
                *(float2*)(Yf + p0 + 8 * (size_t)D_) = make_float2(acc[i][jj][2], acc[i][jj][3]);
            }
    }
}

// ---------------------------------------------------------------------------
// HMMA causal flash attention.
// CTA: 128 queries x one (b,h). 8 warps, 16 query rows each.
// K/V bf16 hi/lo tiles (64 keys x 64 dims) double-buffered via cp.async.
// QK: Qh*Kh + Ql*Kh + Qh*Kl.  PV: (Ph+Pl)*Vh + Ph*Vl.
// Writes bf16 hi/lo split output directly (g_ah/g_al).
// ---------------------------------------------------------------------------
#define AT_BUF 32768   // 4 tensors x 8KB
__global__ __launch_bounds__(256, 1) void attn_hmma()
{
    extern __shared__ char asmem[];
    const uint32_t sb = smem_u32(asmem);
    const int tid = threadIdx.x, wid = tid >> 5, lid = tid & 31;
    const int qt = (int)gridDim.x - 1 - (int)blockIdx.x;   // heavy tiles first
    const int bh = blockIdx.y;
    const int b = bh >> 4, h = bh & 15;
    const int sub = lid >> 3, l7 = lid & 7;
    const int quad = lid >> 2, qlane = lid & 3;

    const int qrow = qt * 128 + wid * 16 + quad;           // low row of pair

    // Q fragments (A operand), hi and lo
    uint32_t Qh[4][4], Ql[4][4];
    {
        const size_t base = (size_t)(b * S_ + qrow) * D_ + h * DK_ + qlane * 2;
        const size_t b8 = base + 8 * (size_t)D_;
#pragma unroll
        for (int ks = 0; ks < 4; ks++) {
            int cc = ks * 16;
            Qh[ks][0] = *(const uint32_t*)(g_qh + base + cc);
            Qh[ks][1] = *(const uint32_t*)(g_qh + b8 + cc);
            Qh[ks][2] = *(const uint32_t*)(g_qh + base + cc + 8);
            Qh[ks][3] = *(const uint32_t*)(g_qh + b8 + cc + 8);
            Ql[ks][0] = *(const uint32_t*)(g_ql + base + cc);
            Ql[ks][1] = *(const uint32_t*)(g_ql + b8 + cc);
            Ql[ks][2] = *(const uint32_t*)(g_ql + base + cc + 8);
            Ql[ks][3] = *(const uint32_t*)(g_ql + b8 + cc + 8);
        }
    }

    float O[8][4];
#pragma unroll
    for (int j = 0; j < 8; j++)
#pragma unroll
        for (int c = 0; c < 4; c++) O[j][c] = 0.f;
    float m0 = -1e30f, m1 = -1e30f, l0 = 0.f, l1 = 0.f;

    const size_t hoff = (size_t)(b * S_) * D_ + h * DK_;
    const __nv_bfloat16* gKh = g_kh + hoff;
    const __nv_bfloat16* gKl = g_kl + hoff;
    const __nv_bfloat16* gVh = g_vh + hoff;
    const __nv_bfloat16* gVl = g_vl + hoff;

    const int crow = tid >> 3;          // 0..31: row within 64 handled below
    const int cc16 = tid & 7;           // 16B chunk in row

    auto issue = [&](int kt) {
        const uint32_t bufb = sb + (uint32_t)(kt & 1) * AT_BUF;
#pragma unroll
        for (int t = 0; t < 8; t++) {
            const int tensor = t >> 1;                       // 0..3 compile-time
            const int row = (t & 1) * 32 + crow;             // 0..63
            const __nv_bfloat16* gp = (tensor == 0) ? gKh : (tensor == 1) ? gKl
                                     : (tensor == 2) ? gVh : gVl;
            cp_async16(bufb + (uint32_t)tensor * 8192 + SWZ((uint32_t)(row * 128 + cc16 * 16)),
                       gp + (size_t)(kt * 64 + row) * D_ + cc16 * 8);
        }
    };

    const int ntiles = 2 * qt + 2;
    issue(0); CP_COMMIT();

    for (int kt = 0; kt < ntiles; kt++) {
        if (kt + 1 < ntiles) { issue(kt + 1); CP_COMMIT(); CP_WAIT(1); }
        else                 { CP_WAIT(0); }
        __syncthreads();

        const uint32_t bufb = sb + (uint32_t)(kt & 1) * AT_BUF;
        const uint32_t sKH = bufb, sKL = bufb + 8192, sVH = bufb + 16384, sVL = bufb + 24576;
        const int kg0 = kt * 64;

        // ---- scores = Q . K^T (split) ----
        float sc[8][4];
#pragma unroll
        for (int j = 0; j < 8; j++)
#pragma unroll
            for (int c = 0; c < 4; c++) sc[j][c] = 0.f;

#pragma unroll
        for (int ks = 0; ks < 4; ks++) {
            uint32_t bK[4][4];
#pragma unroll
            for (int j = 0; j < 4; j++)
                ldsm_x4(bK[j], sKH + SWZ((uint32_t)((j * 16 + (sub >> 1) * 8 + l7) * 128
                                                   + (ks * 16 + (sub & 1) * 8) * 2)));
#pragma unroll
            for (int j = 0; j < 4; j++) {
                mma_16816(sc[2 * j],     Qh[ks], bK[j][0], bK[j][1]);
                mma_16816(sc[2 * j + 1], Qh[ks], bK[j][2], bK[j][3]);
                mma_16816(sc[2 * j],     Ql[ks], bK[j][0], bK[j][1]);
                mma_16816(sc[2 * j + 1], Ql[ks], bK[j][2], bK[j][3]);
            }
#pragma unroll
            for (int j = 0; j < 4; j++)
                ldsm_x4(bK[j], sKL + SWZ((uint32_t)((j * 16 + (sub >> 1) * 8 + l7) * 128
                                                   + (ks * 16 + (sub & 1) * 8) * 2)));
#pragma unroll
            for (int j = 0; j < 4; j++) {
                mma_16816(sc[2 * j],     Qh[ks], bK[j][0], bK[j][1]);
                mma_16816(sc[2 * j + 1], Qh[ks], bK[j][2], bK[j][3]);
            }
        }

        // scale into log2 domain + causal mask
#pragma unroll
        for (int j = 0; j < 8; j++)
#pragma unroll
            for (int c = 0; c < 4; c++) sc[j][c] *= SCALE_C;
        if (kt >= 2 * qt) {
#pragma unroll
            for (int j = 0; j < 8; j++)
#pragma unroll
                for (int c = 0; c < 4; c++) {
                    int kc = kg0 + j * 8 + qlane * 2 + (c & 1);
                    int qr = qrow + ((c >= 2) ? 8 : 0);
                    if (kc > qr) sc[j][c] = -1e30f;
                }
        }

        // ---- online softmax (log2 domain) ----
        float t0 = -1e30f, t1 = -1e30f;
#pragma unroll
        for (int j = 0; j < 8; j++) {
            t0 = fmaxf(t0, fmaxf(sc[j][0], sc[j][1]));
            t1 = fmaxf(t1, fmaxf(sc[j][2], sc[j][3]));
        }
        t0 = fmaxf(t0, __shfl_xor_sync(0xffffffffu, t0, 1));
        t0 = fmaxf(t0, __shfl_xor_sync(0xffffffffu, t0, 2));
        t1 = fmaxf(t1, __shfl_xor_sync(0xffffffffu, t1, 1));
        t1 = fmaxf(t1, __shfl_xor_sync(0xffffffffu, t1, 2));
        float m0n = fmaxf(m0, t0), m1n = fmaxf(m1, t1);
        float cr0 = fexp2(m0 - m0n), cr1 = fexp2(m1 - m1n);
        m0 = m0n; m1 = m1n;

        float s0 = 0.f, s1 = 0.f;
#pragma unroll
        for (int j = 0; j < 8; j++) {
            sc[j][0] = fexp2(sc[j][0] - m0);
            sc[j][1] = fexp2(sc[j][1] - m0);
            sc[j][2] = fexp2(sc[j][2] - m1);
            sc[j][3] = fexp2(sc[j][3] - m1);
            s0 += sc[j][0] + sc[j][1];
            s1 += sc[j][2] + sc[j][3];
        }
        s0 += __shfl_xor_sync(0xffffffffu, s0, 1);
        s0 += __shfl_xor_sync(0xffffffffu, s0, 2);
        s1 += __shfl_xor_sync(0xffffffffu, s1, 1);
        s1 += __shfl_xor_sync(0xffffffffu, s1, 2);
        l0 = l0 * cr0 + s0;
        l1 = l1 * cr1 + s1;
#pragma unroll
        for (int j = 0; j < 8; j++) {
            O[j][0] *= cr0; O[j][1] *= cr0; O[j][2] *= cr1; O[j][3] *= cr1;
        }

        // ---- pack P (hi/lo) as A fragments ----
        uint32_t Ph[4][4], Pl[4][4];
#pragma unroll
        for (int ks = 0; ks < 4; ks++) {
            float* e0 = sc[2 * ks];
            float* e1 = sc[2 * ks + 1];
            Ph[ks][0] = pack_bf16x2(e0[0], e0[1]);
            Ph[ks][1] = pack_bf16x2(e0[2], e0[3]);
            Ph[ks][2] = pack_bf16x2(e1[0], e1[1]);
            Ph[ks][3] = pack_bf16x2(e1[2], e1[3]);
            Pl[ks][0] = pack_bf16x2(e0[0] - bf16lo_f(Ph[ks][0]), e0[1] - bf16hi_f(Ph[ks][0]));
            Pl[ks][1] = pack_bf16x2(e0[2] - bf16lo_f(Ph[ks][1]), e0[3] - bf16hi_f(Ph[ks][1]));
            Pl[ks][2] = pack_bf16x2(e1[0] - bf16lo_f(Ph[ks][2]), e1[1] - bf16hi_f(Ph[ks][2]));
            Pl[ks][3] = pack_bf16x2(e1[2] - bf16lo_f(Ph[ks][3]), e1[3] - bf16hi_f(Ph[ks][3]));
        }

        // ---- O += P . V (split) ----
#pragma unroll
        for (int ks = 0; ks < 4; ks++) {
            uint32_t bV[4][4];
#pragma unroll
            for (int j = 0; j < 4; j++)
                ldsm_x4_t(bV[j], sVH + SWZ((uint32_t)((ks * 16 + (sub & 1) * 8 + l7) * 128
                                                     + (j * 16 + (sub >> 1) * 8) * 2)));
#pragma unroll
            for (int j = 0; j < 4; j++) {
                mma_16816(O[2 * j],     Ph[ks], bV[j][0], bV[j][1]);
                mma_16816(O[2 * j + 1], Ph[ks], bV[j][2], bV[j][3]);
                mma_16816(O[2 * j],     Pl[ks], bV[j][0], bV[j][1]);
                mma_16816(O[2 * j + 1], Pl[ks], bV[j][2], bV[j][3]);
            }
#pragma unroll
            for (int j = 0; j < 4; j++)
                ldsm_x4_t(bV[j], sVL + SWZ((uint32_t)((ks * 16 + (sub & 1) * 8 + l7) * 128
                                                     + (j * 16 + (sub >> 1) * 8) * 2)));
#pragma unroll
            for (int j = 0; j < 4; j++) {
                mma_16816(O[2 * j],     Ph[ks], bV[j][0], bV[j][1]);
                mma_16816(O[2 * j + 1], Ph[ks], bV[j][2], bV[j][3]);
            }
        }
        __syncthreads();
    }

    // ---- epilogue: normalize, split to bf16 hi/lo ----
    const float i0 = 1.f / l0, i1 = 1.f / l1;
    const size_t ob = (size_t)(b * S_ + qrow) * D_ + h * DK_ + qlane * 2;
    const size_t ob8 = ob + 8 * (size_t)D_;
#pragma unroll
    for (int j = 0; j < 8; j++) {
        float v0 = O[j][0] * i0, v1 = O[j][1] * i0;
        float v2 = O[j][2] * i1, v3 = O[j][3] * i1;
        uint32_t h0 = pack_bf16x2(v0, v1);
        uint32_t h1 = pack_bf16x2(v2, v3);
        uint32_t lo0 = pack_bf16x2(v0 - bf16lo_f(h0), v1 - bf16hi_f(h0));
        uint32_t lo1 = pack_bf16x2(v2 - bf16lo_f(h1), v3 - bf16hi_f(h1));
        *(uint32_t*)(g_ah + ob + j * 8)  = h0;
        *(uint32_t*)(g_al + ob + j * 8)  = lo0;
        *(uint32_t*)(g_ah + ob8 + j * 8) = h1;
        *(uint32_t*)(g_al + ob8 + j * 8) = lo1;
    }
}

// ---------------------------------------------------------------------------
extern "C" void kernel_launch(void* const* d_in, const int* in_sizes, int n_in,
                              void* d_out, int out_size)
{
    (void)in_sizes; (void)n_in; (void)out_size;
    const float* q  = (const float*)d_in[0];
    const float* k  = (const float*)d_in[1];
    const float* v  = (const float*)d_in[2];
    const float* Wq = (const float*)d_in[4];
    const float* Wk = (const float*)d_in[5];
    const float* Wv = (const float*)d_in[6];
    const float* Wo = (const float*)d_in[7];
    float* out = (float*)d_out;

    __nv_bfloat16 *xqh, *xql, *xkh, *xkl, *xvh, *xvl;
    __nv_bfloat16 *wqh, *wql, *wkh, *wkl, *wvh, *wvl, *woh, *wol;
    __nv_bfloat16 *qh, *ql, *kh, *kl, *vh, *vl, *ah, *al;
    cudaGetSymbolAddress((void**)&xqh, g_xqh); cudaGetSymbolAddress((void**)&xql, g_xql);
    cudaGetSymbolAddress((void**)&xkh, g_xkh); cudaGetSymbolAddress((void**)&xkl, g_xkl);
    cudaGetSymbolAddress((void**)&xvh, g_xvh); cudaGetSymbolAddress((void**)&xvl, g_xvl);
    cudaGetSymbolAddress((void**)&wqh, g_wqh); cudaGetSymbolAddress((void**)&wql, g_wql);
    cudaGetSymbolAddress((void**)&wkh, g_wkh); cudaGetSymbolAddress((void**)&wkl, g_wkl);
    cudaGetSymbolAddress((void**)&wvh, g_wvh); cudaGetSymbolAddress((void**)&wvl, g_wvl);
    cudaGetSymbolAddress((void**)&woh, g_woh); cudaGetSymbolAddress((void**)&wol, g_wol);
    cudaGetSymbolAddress((void**)&qh, g_qh);   cudaGetSymbolAddress((void**)&ql, g_ql);
    cudaGetSymbolAddress((void**)&kh, g_kh);   cudaGetSymbolAddress((void**)&kl, g_kl);
    cudaGetSymbolAddress((void**)&vh, g_vh);   cudaGetSymbolAddress((void**)&vl, g_vl);
    cudaGetSymbolAddress((void**)&ah, g_ah);   cudaGetSymbolAddress((void**)&al, g_al);

    static int smem_set = 0;
    if (!smem_set) {
        cudaFuncSetAttribute(attn_hmma, cudaFuncAttributeMaxDynamicSharedMemorySize, 2 * AT_BUF);
        smem_set = 1;
    }

    const int n4_big = (M_ * D_) / 4;
    const int n4_w   = (D_ * D_) / 4;

    // 1) split inputs + weights
    split_kernel<<<n4_big / 256, 256>>>(q, xqh, xql, n4_big);
    split_kernel<<<n4_big / 256, 256>>>(k, xkh, xkl, n4_big);
    split_kernel<<<n4_big / 256, 256>>>(v, xvh, xvl, n4_big);
    split_kernel<<<n4_w / 256, 256>>>(Wq, wqh, wql, n4_w);
    split_kernel<<<n4_w / 256, 256>>>(Wk, wkh, wkl, n4_w);
    split_kernel<<<n4_w / 256, 256>>>(Wv, wvh, wvl, n4_w);
    split_kernel<<<n4_w / 256, 256>>>(Wo, woh, wol, n4_w);

    // 2) QKV projections -> bf16 hi/lo outputs directly
    dim3 gproj(D_ / 128, M_ / 128, 3);
    hmma_gemm3<<<gproj, 256>>>(
        xqh, xql, wqh, wql, nullptr, qh, ql,
        xkh, xkl, wkh, wkl, nullptr, kh, kl,
        xvh, xvl, wvh, wvl, nullptr, vh, vl);

    // 3) causal flash attention on tensor cores -> bf16 hi/lo
    dim3 gattn(S_ / 128, B_ * H_);
    attn_hmma<<<gattn, 256, 2 * AT_BUF>>>();

    // 4) output projection -> fp32 d_out
    dim3 gout(D_ / 128, M_ / 128, 1);
    hmma_gemm3<<<gout, 256>>>(
        ah, al, woh, wol, out, nullptr, nullptr,
        ah, al, woh, wol, out, nullptr, nullptr,
        ah, al, woh, wol, out, nullptr, nullptr);
}

// round 5
// speedup vs baseline: 4.2852x; 1.3666x over previous
#include <cuda_runtime.h>
#include <cuda_fp16.h>
#include <cstdint>

#define B_  2
#define S_  2048
#define D_  1024
#define H_  16
#define DK_ 64
#define M_  (B_ * S_)   // 4096

// ---------------------------------------------------------------------------
// Scratch (allocation-free rule: device globals), fp16
// ---------------------------------------------------------------------------
// input splits (A operands of QKV GEMMs): x = xh + xl (22-bit)
__device__ __half g_xqh[M_ * D_], g_xql[M_ * D_];
__device__ __half g_xkh[M_ * D_], g_xkl[M_ * D_];
__device__ __half g_xvh[M_ * D_], g_xvl[M_ * D_];
// weights quantized to single fp16
__device__ __half g_wqh[D_ * D_], g_wkh[D_ * D_], g_wvh[D_ * D_], g_woh[D_ * D_];
// projected Q (split pair), K/V (single fp16)
__device__ __half g_qh[M_ * D_], g_ql[M_ * D_];
__device__ __half g_kh[M_ * D_];
__device__ __half g_vh[M_ * D_];
// attention output split pair (out-proj A operand)
__device__ __half g_ah[M_ * D_], g_al[M_ * D_];

// ---------------------------------------------------------------------------
__device__ __forceinline__ uint32_t smem_u32(const void* p) {
    uint32_t a;
    asm("{ .reg .u64 t; cvta.to.shared.u64 t, %1; cvt.u32.u64 %0, t; }" : "=r"(a) : "l"(p));
    return a;
}
__device__ __forceinline__ void ldsm_x4(uint32_t* r, uint32_t addr) {
    asm volatile("ldmatrix.sync.aligned.m8n8.x4.shared.b16 {%0,%1,%2,%3}, [%4];"
                 : "=r"(r[0]), "=r"(r[1]), "=r"(r[2]), "=r"(r[3]) : "r"(addr));
}
__device__ __forceinline__ void ldsm_x4_t(uint32_t* r, uint32_t addr) {
    asm volatile("ldmatrix.sync.aligned.m8n8.x4.trans.shared.b16 {%0,%1,%2,%3}, [%4];"
                 : "=r"(r[0]), "=r"(r[1]), "=r"(r[2]), "=r"(r[3]) : "r"(addr));
}
__device__ __forceinline__ void mma_16816(float* c, const uint32_t* a, uint32_t b0, uint32_t b1) {
    asm volatile("mma.sync.aligned.m16n8k16.row.col.f32.f16.f16.f32 "
                 "{%0,%1,%2,%3}, {%4,%5,%6,%7}, {%8,%9}, {%0,%1,%2,%3};"
                 : "+f"(c[0]), "+f"(c[1]), "+f"(c[2]), "+f"(c[3])
                 : "r"(a[0]), "r"(a[1]), "r"(a[2]), "r"(a[3]), "r"(b0), "r"(b1));
}
__device__ __forceinline__ void cp_async16(uint32_t saddr, const void* gaddr) {
    asm volatile("cp.async.cg.shared.global [%0], [%1], 16;" :: "r"(saddr), "l"(gaddr));
}
#define CP_COMMIT()  asm volatile("cp.async.commit_group;" ::: "memory")
#define CP_WAIT(n)   asm volatile("cp.async.wait_group %0;" :: "n"(n) : "memory")
#define SWZ(off) ((off) ^ (((off) >> 3) & 0x70))

// pack two floats to fp16x2 (lo half = f0, hi half = f1)
__device__ __forceinline__ uint32_t pack_f16x2(float f0, float f1) {
    __half2 h = __floats2half2_rn(f0, f1);
    return *(uint32_t*)&h;
}
__device__ __forceinline__ float f16lo_f(uint32_t p) { return __low2float(*(__half2*)&p); }
__device__ __forceinline__ float f16hi_f(uint32_t p) { return __high2float(*(__half2*)&p); }

// FFMA-pipe 2^x (rel err ~2e-6)
__device__ __forceinline__ float fexp2(float x) {
    x = fmaxf(x, -126.0f);
    float r = rintf(x);
    float f = x - r;
    float p = 1.3333558e-3f;
    p = fmaf(p, f, 9.6181291e-3f);
    p = fmaf(p, f, 5.5504109e-2f);
    p = fmaf(p, f, 2.4022651e-1f);
    p = fmaf(p, f, 6.9314718e-1f);
    p = fmaf(p, f, 1.0f);
    return p * __int_as_float(((int)r + 127) << 23);
}
#define LOG2E 1.4426950408889634f
#define SCALE_C (0.125f * LOG2E)

// ---------------------------------------------------------------------------
// fp32 -> (fp16 hi, fp16 lo) split
// ---------------------------------------------------------------------------
__global__ __launch_bounds__(256) void split_kernel(const float* __restrict__ src,
                                                    __half* __restrict__ hi,
                                                    __half* __restrict__ lo, int n4)
{
    int idx = blockIdx.x * 256 + threadIdx.x;
    if (idx >= n4) return;
    float4 x = ((const float4*)src)[idx];
    uint32_t h0 = pack_f16x2(x.x, x.y);
    uint32_t h1 = pack_f16x2(x.z, x.w);
    uint32_t l0 = pack_f16x2(x.x - f16lo_f(h0), x.y - f16hi_f(h0));
    uint32_t l1 = pack_f16x2(x.z - f16lo_f(h1), x.w - f16hi_f(h1));
    ((uint2*)hi)[idx] = make_uint2(h0, h1);
    ((uint2*)lo)[idx] = make_uint2(l0, l1);
}
// fp32 -> fp16 convert (weights)
__global__ __launch_bounds__(256) void conv_kernel(const float* __restrict__ src,
                                                   __half* __restrict__ dst, int n4)
{
    int idx = blockIdx.x * 256 + threadIdx.x;
    if (idx >= n4) return;
    float4 x = ((const float4*)src)[idx];
    ((uint2*)dst)[idx] = make_uint2(pack_f16x2(x.x, x.y), pack_f16x2(x.z, x.w));
}

// ---------------------------------------------------------------------------
// HMMA GEMM: Y = X @ W^T, fp16x2 split ((xh+xl)*wh), fp32 acc.
// 128x128 CTA, BK=32, 8 warps. Epilogue: fp32 (Yf) / fp16 split (Yh,Yl) /
// fp16 single (Yh only).
// ---------------------------------------------------------------------------
#define TILE_B 8192
#define NITER  64                    // 2 passes * 32 k-chunks
__device__ __forceinline__ uint32_t tile_off(int row, int k) {
    uint32_t b = ((uint32_t)(row >> 1) << 7) | ((uint32_t)(row & 1) << 6) | ((uint32_t)k << 1);
    return SWZ(b);
}

__global__ __launch_bounds__(256) void hmma_gemm3(
    const __half* __restrict__ Xh0, const __half* __restrict__ Xl0, const __half* __restrict__ Wh0,
    float* Yf0, __half* Yh0, __half* Yl0,
    const __half* __restrict__ Xh1, const __half* __restrict__ Xl1, const __half* __restrict__ Wh1,
    float* Yf1, __half* Yh1, __half* Yl1,
    const __half* __restrict__ Xh2, const __half* __restrict__ Xl2, const __half* __restrict__ Wh2,
    float* Yf2, __half* Yh2, __half* Yl2)
{
    const __half *Xh, *Xl, *Wh; float* Yf; __half *Yh, *Yl;
    if (blockIdx.z == 0)      { Xh=Xh0; Xl=Xl0; Wh=Wh0; Yf=Yf0; Yh=Yh0; Yl=Yl0; }
    else if (blockIdx.z == 1) { Xh=Xh1; Xl=Xl1; Wh=Wh1; Yf=Yf1; Yh=Yh1; Yl=Yl1; }
    else                      { Xh=Xh2; Xl=Xl2; Wh=Wh2; Yf=Yf2; Yh=Yh2; Yl=Yl2; }

    __shared__ char smem[4 * TILE_B];
    const uint32_t sb = smem_u32(smem);

    const int tid = threadIdx.x;
    const int wid = tid >> 5;
    const int lid = tid & 31;
    const int m0 = blockIdx.y * 128;
    const int n0 = blockIdx.x * 128;
    const int wr = (wid & 1) * 64;
    const int wn = (wid >> 1) * 32;

    const int r0 = tid >> 2;
    const int kb = (tid & 3) * 8;
    const uint32_t so0 = tile_off(r0, kb);
    const uint32_t so1 = tile_off(r0 + 64, kb);
    const size_t go0 = (size_t)r0 * D_ + kb;
    const size_t go1 = (size_t)(r0 + 64) * D_ + kb;

    const int sub = lid >> 3, l7 = lid & 7;
    uint32_t offA[2][4], offB[2][2];
#pragma unroll
    for (int ks = 0; ks < 2; ks++) {
#pragma unroll
        for (int i = 0; i < 4; i++)
            offA[ks][i] = tile_off(wr + i * 16 + (sub & 1) * 8 + l7, ks * 16 + (sub >> 1) * 8);
#pragma unroll
        for (int j = 0; j < 2; j++)
            offB[ks][j] = tile_off(wn + j * 16 + (sub >> 1) * 8 + l7, ks * 16 + (sub & 1) * 8);
    }

    float acc[4][4][4];
#pragma unroll
    for (int i = 0; i < 4; i++)
#pragma unroll
        for (int j = 0; j < 4; j++)
#pragma unroll
            for (int c = 0; c < 4; c++) acc[i][j][c] = 0.f;

    auto issue = [&](int it) {
        const int pass = it >> 5;                    // 0: xh  1: xl
        const int k0 = (it & 31) * 32;
        const uint32_t bufb = sb + (uint32_t)(it & 1) * (2 * TILE_B);
        const __half* Ag = pass ? Xl : Xh;
        const __half* Ab = Ag + (size_t)m0 * D_ + k0;
        const __half* Bb = Wh + (size_t)n0 * D_ + k0;
        cp_async16(bufb + so0,          Ab + go0);
        cp_async16(bufb + so1,          Ab + go1);
        cp_async16(bufb + TILE_B + so0, Bb + go0);
        cp_async16(bufb + TILE_B + so1, Bb + go1);
    };

    issue(0); CP_COMMIT();

    for (int it = 0; it < NITER; it++) {
        if (it + 1 < NITER) { issue(it + 1); CP_COMMIT(); CP_WAIT(1); }
        else                { CP_WAIT(0); }
        __syncthreads();

        const uint32_t sA = sb + (uint32_t)(it & 1) * (2 * TILE_B);
        const uint32_t sB = sA + TILE_B;
#pragma unroll
        for (int ks = 0; ks < 2; ks++) {
            uint32_t a[4][4], b[2][4];
#pragma unroll
            for (int i = 0; i < 4; i++) ldsm_x4(a[i], sA + offA[ks][i]);
#pragma unroll
            for (int j = 0; j < 2; j++) ldsm_x4(b[j], sB + offB[ks][j]);
#pragma unroll
            for (int i = 0; i < 4; i++)
#pragma unroll
                for (int jj = 0; jj < 4; jj++)
                    mma_16816(acc[i][jj], a[i], b[jj >> 1][(jj & 1) * 2], b[jj >> 1][(jj & 1) * 2 + 1]);
        }
        __syncthreads();
    }

    const int er = lid >> 2;
    const int ec = (lid & 3) * 2;
#pragma unroll
    for (int i = 0; i < 4; i++)
#pragma unroll
        for (int jj = 0; jj < 4; jj++) {
            size_t p0 = (size_t)(m0 + wr + i * 16 + er) * D_ + n0 + wn + jj * 8 + ec;
            size_t p1 = p0 + 8 * (size_t)D_;
            float* a4 = acc[i][jj];
            if (Yl) {          // fp16 hi/lo split output (Q)
                uint32_t h0 = pack_f16x2(a4[0], a4[1]);
                uint32_t h1 = pack_f16x2(a4[2], a4[3]);
                uint32_t l0 = pack_f16x2(a4[0] - f16lo_f(h0), a4[1] - f16hi_f(h0));
                uint32_t l1 = pack_f16x2(a4[2] - f16lo_f(h1), a4[3] - f16hi_f(h1));
                *(uint32_t*)(Yh + p0) = h0; *(uint32_t*)(Yl + p0) = l0;
                *(uint32_t*)(Yh + p1) = h1; *(uint32_t*)(Yl + p1) = l1;
            } else if (Yh) {   // fp16 single output (K, V)
                *(uint32_t*)(Yh + p0) = pack_f16x2(a4[0], a4[1]);
                *(uint32_t*)(Yh + p1) = pack_f16x2(a4[2], a4[3]);
            } else {           // fp32 output (final)
                *(float2*)(Yf + p0) = make_float2(a4[0], a4[1]);
                *(float2*)(Yf + p1) = make_float2(a4[2], a4[3]);
            }
        }
}

// ---------------------------------------------------------------------------
// HMMA causal flash attention, fp16.
// CTA: 128 queries x one (b,h). 8 warps, 16 query rows each.
// K/V single fp16 tiles (64 keys x 64 dims) double-buffered via cp.async.
// QK: (Qh + Ql) . K.   PV: (Ph + Pl) . V.
// Writes fp16 hi/lo split output (g_ah/g_al).
// ---------------------------------------------------------------------------
#define AT_BUF 16384   // 2 tensors x 8KB
__global__ __launch_bounds__(256, 1) void attn_hmma()
{
    extern __shared__ char asmem[];
    const uint32_t sb = smem_u32(asmem);
    const int tid = threadIdx.x, wid = tid >> 5, lid = tid & 31;
    const int qt = (int)gridDim.x - 1 - (int)blockIdx.x;   // heavy tiles first
    const int bh = blockIdx.y;
    const int b = bh >> 4, h = bh & 15;
    const int sub = lid >> 3, l7 = lid & 7;
    const int quad = lid >> 2, qlane = lid & 3;

    const int qrow = qt * 128 + wid * 16 + quad;

    uint32_t Qh[4][4], Ql[4][4];
    {
        const size_t base = (size_t)(b * S_ + qrow) * D_ + h * DK_ + qlane * 2;
        const size_t b8 = base + 8 * (size_t)D_;
#pragma unroll
        for (int ks = 0; ks < 4; ks++) {
            int cc = ks * 16;
            Qh[ks][0] = *(const uint32_t*)(g_qh + base + cc);
            Qh[ks][1] = *(const uint32_t*)(g_qh + b8 + cc);
            Qh[ks][2] = *(const uint32_t*)(g_qh + base + cc + 8);
            Qh[ks][3] = *(const uint32_t*)(g_qh + b8 + cc + 8);
            Ql[ks][0] = *(const uint32_t*)(g_ql + base + cc);
            Ql[ks][1] = *(const uint32_t*)(g_ql + b8 + cc);
            Ql[ks][2] = *(const uint32_t*)(g_ql + base + cc + 8);
            Ql[ks][3] = *(const uint32_t*)(g_ql + b8 + cc + 8);
        }
    }

    float O[8][4];
#pragma unroll
    for (int j = 0; j < 8; j++)
#pragma unroll
        for (int c = 0; c < 4; c++) O[j][c] = 0.f;
    float m0 = -1e30f, m1 = -1e30f, l0 = 0.f, l1 = 0.f;

    const size_t hoff = (size_t)(b * S_) * D_ + h * DK_;
    const __half* gK = g_kh + hoff;
    const __half* gV = g_vh + hoff;

    const int crow = tid >> 3;
    const int cc16 = tid & 7;

    auto issue = [&](int kt) {
        const uint32_t bufb = sb + (uint32_t)(kt & 1) * AT_BUF;
#pragma unroll
        for (int t = 0; t < 4; t++) {
            const int tensor = t >> 1;                 // 0=K, 1=V
            const int row = (t & 1) * 32 + crow;
            const __half* gp = tensor ? gV : gK;
            cp_async16(bufb + (uint32_t)tensor * 8192 + SWZ((uint32_t)(row * 128 + cc16 * 16)),
                       gp + (size_t)(kt * 64 + row) * D_ + cc16 * 8);
        }
    };

    const int ntiles = 2 * qt + 2;
    issue(0); CP_COMMIT();

    for (int kt = 0; kt < ntiles; kt++) {
        if (kt + 1 < ntiles) { issue(kt + 1); CP_COMMIT(); CP_WAIT(1); }
        else                 { CP_WAIT(0); }
        __syncthreads();

        const uint32_t bufb = sb + (uint32_t)(kt & 1) * AT_BUF;
        const uint32_t sK = bufb, sV = bufb + 8192;
        const int kg0 = kt * 64;

        // ---- scores = (Qh + Ql) . K^T ----
        float sc[8][4];
#pragma unroll
        for (int j = 0; j < 8; j++)
#pragma unroll
            for (int c = 0; c < 4; c++) sc[j][c] = 0.f;

#pragma unroll
        for (int ks = 0; ks < 4; ks++) {
            uint32_t bK[4][4];
#pragma unroll
            for (int j = 0; j < 4; j++)
                ldsm_x4(bK[j], sK + SWZ((uint32_t)((j * 16 + (sub >> 1) * 8 + l7) * 128
                                                  + (ks * 16 + (sub & 1) * 8) * 2)));
#pragma unroll
            for (int j = 0; j < 4; j++) {
                mma_16816(sc[2 * j],     Qh[ks], bK[j][0], bK[j][1]);
                mma_16816(sc[2 * j + 1], Qh[ks], bK[j][2], bK[j][3]);
                mma_16816(sc[2 * j],     Ql[ks], bK[j][0], bK[j][1]);
                mma_16816(sc[2 * j + 1], Ql[ks], bK[j][2], bK[j][3]);
            }
        }

#pragma unroll
        for (int j = 0; j < 8; j++)
#pragma unroll
            for (int c = 0; c < 4; c++) sc[j][c] *= SCALE_C;
        if (kt >= 2 * qt) {
#pragma unroll
            for (int j = 0; j < 8; j++)
#pragma unroll
                for (int c = 0; c < 4; c++) {
                    int kc = kg0 + j * 8 + qlane * 2 + (c & 1);
                    int qr = qrow + ((c >= 2) ? 8 : 0);
                    if (kc > qr) sc[j][c] = -1e30f;
                }
        }

        // ---- online softmax (log2 domain) ----
        float t0 = -1e30f, t1 = -1e30f;
#pragma unroll
        for (int j = 0; j < 8; j++) {
            t0 = fmaxf(t0, fmaxf(sc[j][0], sc[j][1]));
            t1 = fmaxf(t1, fmaxf(sc[j][2], sc[j][3]));
        }
        t0 = fmaxf(t0, __shfl_xor_sync(0xffffffffu, t0, 1));
        t0 = fmaxf(t0, __shfl_xor_sync(0xffffffffu, t0, 2));
        t1 = fmaxf(t1, __shfl_xor_sync(0xffffffffu, t1, 1));
        t1 = fmaxf(t1, __shfl_xor_sync(0xffffffffu, t1, 2));
        float m0n = fmaxf(m0, t0), m1n = fmaxf(m1, t1);
        float cr0 = fexp2(m0 - m0n), cr1 = fexp2(m1 - m1n);
        m0 = m0n; m1 = m1n;

        float s0 = 0.f, s1 = 0.f;
#pragma unroll
        for (int j = 0; j < 8; j++) {
            sc[j][0] = fexp2(sc[j][0] - m0);
            sc[j][1] = fexp2(sc[j][1] - m0);
            sc[j][2] = fexp2(sc[j][2] - m1);
            sc[j][3] = fexp2(sc[j][3] - m1);
            s0 += sc[j][0] + sc[j][1];
            s1 += sc[j][2] + sc[j][3];
        }
        s0 += __shfl_xor_sync(0xffffffffu, s0, 1);
        s0 += __shfl_xor_sync(0xffffffffu, s0, 2);
        s1 += __shfl_xor_sync(0xffffffffu, s1, 1);
        s1 += __shfl_xor_sync(0xffffffffu, s1, 2);
        l0 = l0 * cr0 + s0;
        l1 = l1 * cr1 + s1;
#pragma unroll
        for (int j = 0; j < 8; j++) {
            O[j][0] *= cr0; O[j][1] *= cr0; O[j][2] *= cr1; O[j][3] *= cr1;
        }

        // ---- pack P (hi/lo fp16) as A fragments ----
        uint32_t Ph[4][4], Pl[4][4];
#pragma unroll
        for (int ks = 0; ks < 4; ks++) {
            float* e0 = sc[2 * ks];
            float* e1 = sc[2 * ks + 1];
            Ph[ks][0] = pack_f16x2(e0[0], e0[1]);
            Ph[ks][1] = pack_f16x2(e0[2], e0[3]);
            Ph[ks][2] = pack_f16x2(e1[0], e1[1]);
            Ph[ks][3] = pack_f16x2(e1[2], e1[3]);
            Pl[ks][0] = pack_f16x2(e0[0] - f16lo_f(Ph[ks][0]), e0[1] - f16hi_f(Ph[ks][0]));
            Pl[ks][1] = pack_f16x2(e0[2] - f16lo_f(Ph[ks][1]), e0[3] - f16hi_f(Ph[ks][1]));
            Pl[ks][2] = pack_f16x2(e1[0] - f16lo_f(Ph[ks][2]), e1[1] - f16hi_f(Ph[ks][2]));
            Pl[ks][3] = pack_f16x2(e1[2] - f16lo_f(Ph[ks][3]), e1[3] - f16hi_f(Ph[ks][3]));
        }

        // ---- O += (Ph + Pl) . V ----
#pragma unroll
        for (int ks = 0; ks < 4; ks++) {
            uint32_t bV[4][4];
#pragma unroll
            for (int j = 0; j < 4; j++)
                ldsm_x4_t(bV[j], sV + SWZ((uint32_t)((ks * 16 + (sub & 1) * 8 + l7) * 128
                                                    + (j * 16 + (sub >> 1) * 8) * 2)));
#pragma unroll
            for (int j = 0; j < 4; j++) {
                mma_16816(O[2 * j],     Ph[ks], bV[j][0], bV[j][1]);
                mma_16816(O[2 * j + 1], Ph[ks], bV[j][2], bV[j][3]);
                mma_16816(O[2 * j],     Pl[ks], bV[j][0], bV[j][1]);
                mma_16816(O[2 * j + 1], Pl[ks], bV[j][2], bV[j][3]);
            }
        }
        __syncthreads();
    }

    // ---- epilogue: normalize, split to fp16 hi/lo ----
    const float i0 = 1.f / l0, i1 = 1.f / l1;
    const size_t ob = (size_t)(b * S_ + qrow) * D_ + h * DK_ + qlane * 2;
    const size_t ob8 = ob + 8 * (size_t)D_;
#pragma unroll
    for (int j = 0; j < 8; j++) {
        float v0 = O[j][0] * i0, v1 = O[j][1] * i0;
        float v2 = O[j][2] * i1, v3 = O[j][3] * i1;
        uint32_t h0 = pack_f16x2(v0, v1);
        uint32_t h1 = pack_f16x2(v2, v3);
        uint32_t lo0 = pack_f16x2(v0 - f16lo_f(h0), v1 - f16hi_f(h0));
        uint32_t lo1 = pack_f16x2(v2 - f16lo_f(h1), v3 - f16hi_f(h1));
        *(uint32_t*)(g_ah + ob + j * 8)  = h0;
        *(uint32_t*)(g_al + ob + j * 8)  = lo0;
        *(uint32_t*)(g_ah + ob8 + j * 8) = h1;
        *(uint32_t*)(g_al + ob8 + j * 8) = lo1;
    }
}

// ---------------------------------------------------------------------------
extern "C" void kernel_launch(void* const* d_in, const int* in_sizes, int n_in,
                              void* d_out, int out_size)
{
    (void)in_sizes; (void)n_in; (void)out_size;
    const float* q  = (const float*)d_in[0];
    const float* k  = (const float*)d_in[1];
    const float* v  = (const float*)d_in[2];
    const float* Wq = (const float*)d_in[4];
    const float* Wk = (const float*)d_in[5];
    const float* Wv = (const float*)d_in[6];
    const float* Wo = (const float*)d_in[7];
    float* out = (float*)d_out;

    __half *xqh, *xql, *xkh, *xkl, *xvh, *xvl;
    __half *wqh, *wkh, *wvh, *woh;
    __half *qh, *ql, *kh, *vh, *ah, *al;
    cudaGetSymbolAddress((void**)&xqh, g_xqh); cudaGetSymbolAddress((void**)&xql, g_xql);
    cudaGetSymbolAddress((void**)&xkh, g_xkh); cudaGetSymbolAddress((void**)&xkl, g_xkl);
    cudaGetSymbolAddress((void**)&xvh, g_xvh); cudaGetSymbolAddress((void**)&xvl, g_xvl);
    cudaGetSymbolAddress((void**)&wqh, g_wqh); cudaGetSymbolAddress((void**)&wkh, g_wkh);
    cudaGetSymbolAddress((void**)&wvh, g_wvh); cudaGetSymbolAddress((void**)&woh, g_woh);
    cudaGetSymbolAddress((void**)&qh, g_qh);   cudaGetSymbolAddress((void**)&ql, g_ql);
    cudaGetSymbolAddress((void**)&kh, g_kh);   cudaGetSymbolAddress((void**)&vh, g_vh);
    cudaGetSymbolAddress((void**)&ah, g_ah);   cudaGetSymbolAddress((void**)&al, g_al);

    static int smem_set = 0;
    if (!smem_set) {
        cudaFuncSetAttribute(attn_hmma, cudaFuncAttributeMaxDynamicSharedMemorySize, 2 * AT_BUF);
        smem_set = 1;
    }

    const int n4_big = (M_ * D_) / 4;
    const int n4_w   = (D_ * D_) / 4;

    // 1) split activations (hi/lo), quantize weights (fp16)
    split_kernel<<<n4_big / 256, 256>>>(q, xqh, xql, n4_big);
    split_kernel<<<n4_big / 256, 256>>>(k, xkh, xkl, n4_big);
    split_kernel<<<n4_big / 256, 256>>>(v, xvh, xvl, n4_big);
    conv_kernel<<<n4_w / 256, 256>>>(Wq, wqh, n4_w);
    conv_kernel<<<n4_w / 256, 256>>>(Wk, wkh, n4_w);
    conv_kernel<<<n4_w / 256, 256>>>(Wv, wvh, n4_w);
    conv_kernel<<<n4_w / 256, 256>>>(Wo, woh, n4_w);

    // 2) QKV projections: Q -> split pair, K/V -> single fp16
    dim3 gproj(D_ / 128, M_ / 128, 3);
    hmma_gemm3<<<gproj, 256>>>(
        xqh, xql, wqh, nullptr, qh, ql,
        xkh, xkl, wkh, nullptr, kh, nullptr,
        xvh, xvl, wvh, nullptr, vh, nullptr);

    // 3) causal flash attention -> fp16 hi/lo
    dim3 gattn(S_ / 128, B_ * H_);
    attn_hmma<<<gattn, 256, 2 * AT_BUF>>>();

    // 4) output projection -> fp32 d_out
    dim3 gout(D_ / 128, M_ / 128, 1);
    hmma_gemm3<<<gout, 256>>>(
        ah, al, woh, out, nullptr, nullptr,
        ah, al, woh, out, nullptr, nullptr,
        ah, al, woh, out, nullptr, nullptr);
}

// round 6
// speedup vs baseline: 5.5029x; 1.2841x over previous
#include <cuda_runtime.h>
#include <cuda_fp16.h>
#include <cstdint>

#define B_  2
#define S_  2048
#define D_  1024
#define H_  16
#define DK_ 64
#define M_  (B_ * S_)   // 4096

// ---------------------------------------------------------------------------
// Scratch (allocation-free rule: device globals), fp16
// ---------------------------------------------------------------------------
__device__ __half g_xqh[M_ * D_], g_xql[M_ * D_];          // q input split
__device__ __half g_xkh[M_ * D_], g_xvh[M_ * D_];          // k/v input single fp16
__device__ __half g_wqh[D_ * D_], g_wkh[D_ * D_], g_wvh[D_ * D_], g_woh[D_ * D_];
__device__ __half g_qh[M_ * D_], g_ql[M_ * D_];            // projected Q split
__device__ __half g_kh[M_ * D_];                           // projected K fp16
__device__ __half g_vh[M_ * D_];                           // projected V fp16
__device__ __half g_ah[M_ * D_], g_al[M_ * D_];            // attention out split

// ---------------------------------------------------------------------------
__device__ __forceinline__ uint32_t smem_u32(const void* p) {
    uint32_t a;
    asm("{ .reg .u64 t; cvta.to.shared.u64 t, %1; cvt.u32.u64 %0, t; }" : "=r"(a) : "l"(p));
    return a;
}
__device__ __forceinline__ void ldsm_x4(uint32_t* r, uint32_t addr) {
    asm volatile("ldmatrix.sync.aligned.m8n8.x4.shared.b16 {%0,%1,%2,%3}, [%4];"
                 : "=r"(r[0]), "=r"(r[1]), "=r"(r[2]), "=r"(r[3]) : "r"(addr));
}
__device__ __forceinline__ void ldsm_x4_t(uint32_t* r, uint32_t addr) {
    asm volatile("ldmatrix.sync.aligned.m8n8.x4.trans.shared.b16 {%0,%1,%2,%3}, [%4];"
                 : "=r"(r[0]), "=r"(r[1]), "=r"(r[2]), "=r"(r[3]) : "r"(addr));
}
__device__ __forceinline__ void mma_16816(float* c, const uint32_t* a, uint32_t b0, uint32_t b1) {
    asm volatile("mma.sync.aligned.m16n8k16.row.col.f32.f16.f16.f32 "
                 "{%0,%1,%2,%3}, {%4,%5,%6,%7}, {%8,%9}, {%0,%1,%2,%3};"
                 : "+f"(c[0]), "+f"(c[1]), "+f"(c[2]), "+f"(c[3])
                 : "r"(a[0]), "r"(a[1]), "r"(a[2]), "r"(a[3]), "r"(b0), "r"(b1));
}
__device__ __forceinline__ void cp_async16(uint32_t saddr, const void* gaddr) {
    asm volatile("cp.async.cg.shared.global [%0], [%1], 16;" :: "r"(saddr), "l"(gaddr));
}
#define CP_COMMIT()  asm volatile("cp.async.commit_group;" ::: "memory")
#define CP_WAIT(n)   asm volatile("cp.async.wait_group %0;" :: "n"(n) : "memory")
#define SWZ(off) ((off) ^ (((off) >> 3) & 0x70))

__device__ __forceinline__ uint32_t pack_f16x2(float f0, float f1) {
    __half2 h = __floats2half2_rn(f0, f1);
    return *(uint32_t*)&h;
}
__device__ __forceinline__ float f16lo_f(uint32_t p) { return __low2float(*(__half2*)&p); }
__device__ __forceinline__ float f16hi_f(uint32_t p) { return __high2float(*(__half2*)&p); }

// FFMA-pipe 2^x (rel err ~2e-6)
__device__ __forceinline__ float fexp2(float x) {
    x = fmaxf(x, -126.0f);
    float r = rintf(x);
    float f = x - r;
    float p = 1.3333558e-3f;
    p = fmaf(p, f, 9.6181291e-3f);
    p = fmaf(p, f, 5.5504109e-2f);
    p = fmaf(p, f, 2.4022651e-1f);
    p = fmaf(p, f, 6.9314718e-1f);
    p = fmaf(p, f, 1.0f);
    return p * __int_as_float(((int)r + 127) << 23);
}
#define LOG2E 1.4426950408889634f
#define SCALE_C (0.125f * LOG2E)

// ---------------------------------------------------------------------------
// Fused preprocess: z=0 split q; z=1 conv k; z=2 conv v; z=3..6 conv weights.
// ---------------------------------------------------------------------------
__global__ __launch_bounds__(256) void prep_kernel(
    const float* __restrict__ q, const float* __restrict__ k, const float* __restrict__ v,
    const float* __restrict__ Wq, const float* __restrict__ Wk,
    const float* __restrict__ Wv, const float* __restrict__ Wo)
{
    const int z = blockIdx.z;
    const int idx = blockIdx.x * 256 + threadIdx.x;
    const int n4 = (z < 3) ? (M_ * D_ / 4) : (D_ * D_ / 4);
    if (idx >= n4) return;

    const float* src;
    __half* dst;
    switch (z) {
        case 0: src = q;  dst = g_xqh; break;
        case 1: src = k;  dst = g_xkh; break;
        case 2: src = v;  dst = g_xvh; break;
        case 3: src = Wq; dst = g_wqh; break;
        case 4: src = Wk; dst = g_wkh; break;
        case 5: src = Wv; dst = g_wvh; break;
        default: src = Wo; dst = g_woh; break;
    }
    float4 x = ((const float4*)src)[idx];
    uint32_t h0 = pack_f16x2(x.x, x.y);
    uint32_t h1 = pack_f16x2(x.z, x.w);
    ((uint2*)dst)[idx] = make_uint2(h0, h1);
    if (z == 0) {   // also produce lo residual for q
        uint32_t l0 = pack_f16x2(x.x - f16lo_f(h0), x.y - f16hi_f(h0));
        uint32_t l1 = pack_f16x2(x.z - f16lo_f(h1), x.w - f16hi_f(h1));
        ((uint2*)g_xql)[idx] = make_uint2(l0, l1);
    }
}

// ---------------------------------------------------------------------------
// HMMA GEMM: Y = X @ W^T, fp32 acc. 128x128 CTA, BK=32, 8 warps.
// Passes: 2 if Xl != null ((xh+xl)*w), else 1 (xh*w).
// Epilogue: fp32 (Yf) / fp16 split (Yh,Yl) / fp16 single (Yh).
// ---------------------------------------------------------------------------
#define TILE_B 8192
__device__ __forceinline__ uint32_t tile_off(int row, int k) {
    uint32_t b = ((uint32_t)(row >> 1) << 7) | ((uint32_t)(row & 1) << 6) | ((uint32_t)k << 1);
    return SWZ(b);
}

__global__ __launch_bounds__(256) void hmma_gemm3(
    const __half* __restrict__ Xh0, const __half* __restrict__ Xl0, const __half* __restrict__ Wh0,
    float* Yf0, __half* Yh0, __half* Yl0,
    const __half* __restrict__ Xh1, const __half* __restrict__ Xl1, const __half* __restrict__ Wh1,
    float* Yf1, __half* Yh1, __half* Yl1,
    const __half* __restrict__ Xh2, const __half* __restrict__ Xl2, const __half* __restrict__ Wh2,
    float* Yf2, __half* Yh2, __half* Yl2)
{
    const __half *Xh, *Xl, *Wh; float* Yf; __half *Yh, *Yl;
    if (blockIdx.z == 0)      { Xh=Xh0; Xl=Xl0; Wh=Wh0; Yf=Yf0; Yh=Yh0; Yl=Yl0; }
    else if (blockIdx.z == 1) { Xh=Xh1; Xl=Xl1; Wh=Wh1; Yf=Yf1; Yh=Yh1; Yl=Yl1; }
    else                      { Xh=Xh2; Xl=Xl2; Wh=Wh2; Yf=Yf2; Yh=Yh2; Yl=Yl2; }
    const int niter = Xl ? 64 : 32;            // 2 or 1 passes x 32 k-chunks

    __shared__ char smem[4 * TILE_B];
    const uint32_t sb = smem_u32(smem);

    const int tid = threadIdx.x;
    const int wid = tid >> 5;
    const int lid = tid & 31;
    const int m0 = blockIdx.y * 128;
    const int n0 = blockIdx.x * 128;
    const int wr = (wid & 1) * 64;
    const int wn = (wid >> 1) * 32;

    const int r0 = tid >> 2;
    const int kb = (tid & 3) * 8;
    const uint32_t so0 = tile_off(r0, kb);
    const uint32_t so1 = tile_off(r0 + 64, kb);
    const size_t go0 = (size_t)r0 * D_ + kb;
    const size_t go1 = (size_t)(r0 + 64) * D_ + kb;

    const int sub = lid >> 3, l7 = lid & 7;
    uint32_t offA[2][4], offB[2][2];
#pragma unroll
    for (int ks = 0; ks < 2; ks++) {
#pragma unroll
        for (int i = 0; i < 4; i++)
            offA[ks][i] = tile_off(wr + i * 16 + (sub & 1) * 8 + l7, ks * 16 + (sub >> 1) * 8);
#pragma unroll
        for (int j = 0; j < 2; j++)
            offB[ks][j] = tile_off(wn + j * 16 + (sub >> 1) * 8 + l7, ks * 16 + (sub & 1) * 8);
    }

    float acc[4][4][4];
#pragma unroll
    for (int i = 0; i < 4; i++)
#pragma unroll
        for (int j = 0; j < 4; j++)
#pragma unroll
            for (int c = 0; c < 4; c++) acc[i][j][c] = 0.f;

    auto issue = [&](int it) {
        const int pass = it >> 5;                    // 0: xh  1: xl
        const int k0 = (it & 31) * 32;
        const uint32_t bufb = sb + (uint32_t)(it & 1) * (2 * TILE_B);
        const __half* Ag = pass ? Xl : Xh;
        const __half* Ab = Ag + (size_t)m0 * D_ + k0;
        const __half* Bb = Wh + (size_t)n0 * D_ + k0;
        cp_async16(bufb + so0,          Ab + go0);
        cp_async16(bufb + so1,          Ab + go1);
        cp_async16(bufb + TILE_B + so0, Bb + go0);
        cp_async16(bufb + TILE_B + so1, Bb + go1);
    };

    issue(0); CP_COMMIT();

    for (int it = 0; it < niter; it++) {
        if (it + 1 < niter) { issue(it + 1); CP_COMMIT(); CP_WAIT(1); }
        else                { CP_WAIT(0); }
        __syncthreads();

        const uint32_t sA = sb + (uint32_t)(it & 1) * (2 * TILE_B);
        const uint32_t sB = sA + TILE_B;
#pragma unroll
        for (int ks = 0; ks < 2; ks++) {
            uint32_t a[4][4], b[2][4];
#pragma unroll
            for (int i = 0; i < 4; i++) ldsm_x4(a[i], sA + offA[ks][i]);
#pragma unroll
            for (int j = 0; j < 2; j++) ldsm_x4(b[j], sB + offB[ks][j]);
#pragma unroll
            for (int i = 0; i < 4; i++)
#pragma unroll
                for (int jj = 0; jj < 4; jj++)
                    mma_16816(acc[i][jj], a[i], b[jj >> 1][(jj & 1) * 2], b[jj >> 1][(jj & 1) * 2 + 1]);
        }
        __syncthreads();
    }

    const int er = lid >> 2;
    const int ec = (lid & 3) * 2;
#pragma unroll
    for (int i = 0; i < 4; i++)
#pragma unroll
        for (int jj = 0; jj < 4; jj++) {
            size_t p0 = (size_t)(m0 + wr + i * 16 + er) * D_ + n0 + wn + jj * 8 + ec;
            size_t p1 = p0 + 8 * (size_t)D_;
            float* a4 = acc[i][jj];
            if (Yl) {          // fp16 hi/lo split output (Q, attn-out)
                uint32_t h0 = pack_f16x2(a4[0], a4[1]);
                uint32_t h1 = pack_f16x2(a4[2], a4[3]);
                uint32_t l0 = pack_f16x2(a4[0] - f16lo_f(h0), a4[1] - f16hi_f(h0));
                uint32_t l1 = pack_f16x2(a4[2] - f16lo_f(h1), a4[3] - f16hi_f(h1));
                *(uint32_t*)(Yh + p0) = h0; *(uint32_t*)(Yl + p0) = l0;
                *(uint32_t*)(Yh + p1) = h1; *(uint32_t*)(Yl + p1) = l1;
            } else if (Yh) {   // fp16 single output (K, V)
                *(uint32_t*)(Yh + p0) = pack_f16x2(a4[0], a4[1]);
                *(uint32_t*)(Yh + p1) = pack_f16x2(a4[2], a4[3]);
            } else {           // fp32 output (final)
                *(float2*)(Yf + p0) = make_float2(a4[0], a4[1]);
                *(float2*)(Yf + p1) = make_float2(a4[2], a4[3]);
            }
        }
}

// ---------------------------------------------------------------------------
// HMMA causal flash attention, fp16.
// QK: (Qh + Ql) . K (2 passes).  PV: Ph . V (1 pass).
// ---------------------------------------------------------------------------
#define AT_BUF 16384   // K + V tiles, 8KB each
__global__ __launch_bounds__(256, 1) void attn_hmma()
{
    extern __shared__ char asmem[];
    const uint32_t sb = smem_u32(asmem);
    const int tid = threadIdx.x, wid = tid >> 5, lid = tid & 31;
    const int qt = (int)gridDim.x - 1 - (int)blockIdx.x;   // heavy tiles first
    const int bh = blockIdx.y;
    const int b = bh >> 4, h = bh & 15;
    const int sub = lid >> 3, l7 = lid & 7;
    const int quad = lid >> 2, qlane = lid & 3;

    const int qrow = qt * 128 + wid * 16 + quad;

    uint32_t Qh[4][4], Ql[4][4];
    {
        const size_t base = (size_t)(b * S_ + qrow) * D_ + h * DK_ + qlane * 2;
        const size_t b8 = base + 8 * (size_t)D_;
#pragma unroll
        for (int ks = 0; ks < 4; ks++) {
            int cc = ks * 16;
            Qh[ks][0] = *(const uint32_t*)(g_qh + base + cc);
            Qh[ks][1] = *(const uint32_t*)(g_qh + b8 + cc);
            Qh[ks][2] = *(const uint32_t*)(g_qh + base + cc + 8);
            Qh[ks][3] = *(const uint32_t*)(g_qh + b8 + cc + 8);
            Ql[ks][0] = *(const uint32_t*)(g_ql + base + cc);
            Ql[ks][1] = *(const uint32_t*)(g_ql + b8 + cc);
            Ql[ks][2] = *(const uint32_t*)(g_ql + base + cc + 8);
            Ql[ks][3] = *(const uint32_t*)(g_ql + b8 + cc + 8);
        }
    }

    float O[8][4];
#pragma unroll
    for (int j = 0; j < 8; j++)
#pragma unroll
        for (int c = 0; c < 4; c++) O[j][c] = 0.f;
    float m0 = -1e30f, m1 = -1e30f, l0 = 0.f, l1 = 0.f;

    const size_t hoff = (size_t)(b * S_) * D_ + h * DK_;
    const __half* gK = g_kh + hoff;
    const __half* gV = g_vh + hoff;

    const int crow = tid >> 3;
    const int cc16 = tid & 7;

    auto issue = [&](int kt) {
        const uint32_t bufb = sb + (uint32_t)(kt & 1) * AT_BUF;
#pragma unroll
        for (int t = 0; t < 4; t++) {
            const int tensor = t >> 1;                 // 0=K, 1=V
            const int row = (t & 1) * 32 + crow;
            const __half* gp = tensor ? gV : gK;
            cp_async16(bufb + (uint32_t)tensor * 8192 + SWZ((uint32_t)(row * 128 + cc16 * 16)),
                       gp + (size_t)(kt * 64 + row) * D_ + cc16 * 8);
        }
    };

    const int ntiles = 2 * qt + 2;
    issue(0); CP_COMMIT();

    for (int kt = 0; kt < ntiles; kt++) {
        if (kt + 1 < ntiles) { issue(kt + 1); CP_COMMIT(); CP_WAIT(1); }
        else                 { CP_WAIT(0); }
        __syncthreads();

        const uint32_t bufb = sb + (uint32_t)(kt & 1) * AT_BUF;
        const uint32_t sK = bufb, sV = bufb + 8192;
        const int kg0 = kt * 64;

        // ---- scores = (Qh + Ql) . K^T ----
        float sc[8][4];
#pragma unroll
        for (int j = 0; j < 8; j++)
#pragma unroll
            for (int c = 0; c < 4; c++) sc[j][c] = 0.f;

#pragma unroll
        for (int ks = 0; ks < 4; ks++) {
            uint32_t bK[4][4];
#pragma unroll
            for (int j = 0; j < 4; j++)
                ldsm_x4(bK[j], sK + SWZ((uint32_t)((j * 16 + (sub >> 1) * 8 + l7) * 128
                                                  + (ks * 16 + (sub & 1) * 8) * 2)));
#pragma unroll
            for (int j = 0; j < 4; j++) {
                mma_16816(sc[2 * j],     Qh[ks], bK[j][0], bK[j][1]);
                mma_16816(sc[2 * j + 1], Qh[ks], bK[j][2], bK[j][3]);
                mma_16816(sc[2 * j],     Ql[ks], bK[j][0], bK[j][1]);
                mma_16816(sc[2 * j + 1], Ql[ks], bK[j][2], bK[j][3]);
            }
        }

#pragma unroll
        for (int j = 0; j < 8; j++)
#pragma unroll
            for (int c = 0; c < 4; c++) sc[j][c] *= SCALE_C;
        if (kt >= 2 * qt) {
#pragma unroll
            for (int j = 0; j < 8; j++)
#pragma unroll
                for (int c = 0; c < 4; c++) {
                    int kc = kg0 + j * 8 + qlane * 2 + (c & 1);
                    int qr = qrow + ((c >= 2) ? 8 : 0);
                    if (kc > qr) sc[j][c] = -1e30f;
                }
        }

        // ---- online softmax (log2 domain) ----
        float t0 = -1e30f, t1 = -1e30f;
#pragma unroll
        for (int j = 0; j < 8; j++) {
            t0 = fmaxf(t0, fmaxf(sc[j][0], sc[j][1]));
            t1 = fmaxf(t1, fmaxf(sc[j][2], sc[j][3]));
        }
        t0 = fmaxf(t0, __shfl_xor_sync(0xffffffffu, t0, 1));
        t0 = fmaxf(t0, __shfl_xor_sync(0xffffffffu, t0, 2));
        t1 = fmaxf(t1, __shfl_xor_sync(0xffffffffu, t1, 1));
        t1 = fmaxf(t1, __shfl_xor_sync(0xffffffffu, t1, 2));
        float m0n = fmaxf(m0, t0), m1n = fmaxf(m1, t1);
        float cr0 = fexp2(m0 - m0n), cr1 = fexp2(m1 - m1n);
        m0 = m0n; m1 = m1n;

        float s0 = 0.f, s1 = 0.f;
#pragma unroll
        for (int j = 0; j < 8; j++) {
            sc[j][0] = fexp2(sc[j][0] - m0);
            sc[j][1] = fexp2(sc[j][1] - m0);
            sc[j][2] = fexp2(sc[j][2] - m1);
            sc[j][3] = fexp2(sc[j][3] - m1);
            s0 += sc[j][0] + sc[j][1];
            s1 += sc[j][2] + sc[j][3];
        }
        s0 += __shfl_xor_sync(0xffffffffu, s0, 1);
        s0 += __shfl_xor_sync(0xffffffffu, s0, 2);
        s1 += __shfl_xor_sync(0xffffffffu, s1, 1);
        s1 += __shfl_xor_sync(0xffffffffu, s1, 2);
        l0 = l0 * cr0 + s0;
        l1 = l1 * cr1 + s1;
#pragma unroll
        for (int j = 0; j < 8; j++) {
            O[j][0] *= cr0; O[j][1] *= cr0; O[j][2] *= cr1; O[j][3] *= cr1;
        }

        // ---- pack P (fp16, single) as A fragments ----
        uint32_t Ph[4][4];
#pragma unroll
        for (int ks = 0; ks < 4; ks++) {
            float* e0 = sc[2 * ks];
            float* e1 = sc[2 * ks + 1];
            Ph[ks][0] = pack_f16x2(e0[0], e0[1]);
            Ph[ks][1] = pack_f16x2(e0[2], e0[3]);
            Ph[ks][2] = pack_f16x2(e1[0], e1[1]);
            Ph[ks][3] = pack_f16x2(e1[2], e1[3]);
        }

        // ---- O += Ph . V ----
#pragma unroll
        for (int ks = 0; ks < 4; ks++) {
            uint32_t bV[4][4];
#pragma unroll
            for (int j = 0; j < 4; j++)
                ldsm_x4_t(bV[j], sV + SWZ((uint32_t)((ks * 16 + (sub & 1) * 8 + l7) * 128
                                                    + (j * 16 + (sub >> 1) * 8) * 2)));
#pragma unroll
            for (int j = 0; j < 4; j++) {
                mma_16816(O[2 * j],     Ph[ks], bV[j][0], bV[j][1]);
                mma_16816(O[2 * j + 1], Ph[ks], bV[j][2], bV[j][3]);
            }
        }
        __syncthreads();
    }

    // ---- epilogue: normalize, split to fp16 hi/lo ----
    const float i0 = 1.f / l0, i1 = 1.f / l1;
    const size_t ob = (size_t)(b * S_ + qrow) * D_ + h * DK_ + qlane * 2;
    const size_t ob8 = ob + 8 * (size_t)D_;
#pragma unroll
    for (int j = 0; j < 8; j++) {
        float v0 = O[j][0] * i0, v1 = O[j][1] * i0;
        float v2 = O[j][2] * i1, v3 = O[j][3] * i1;
        uint32_t h0 = pack_f16x2(v0, v1);
        uint32_t h1 = pack_f16x2(v2, v3);
        uint32_t lo0 = pack_f16x2(v0 - f16lo_f(h0), v1 - f16hi_f(h0));
        uint32_t lo1 = pack_f16x2(v2 - f16lo_f(h1), v3 - f16hi_f(h1));
        *(uint32_t*)(g_ah + ob + j * 8)  = h0;
        *(uint32_t*)(g_al + ob + j * 8)  = lo0;
        *(uint32_t*)(g_ah + ob8 + j * 8) = h1;
        *(uint32_t*)(g_al + ob8 + j * 8) = lo1;
    }
}

// ---------------------------------------------------------------------------
extern "C" void kernel_launch(void* const* d_in, const int* in_sizes, int n_in,
                              void* d_out, int out_size)
{
    (void)in_sizes; (void)n_in; (void)out_size;
    const float* q  = (const float*)d_in[0];
    const float* k  = (const float*)d_in[1];
    const float* v  = (const float*)d_in[2];
    const float* Wq = (const float*)d_in[4];
    const float* Wk = (const float*)d_in[5];
    const float* Wv = (const float*)d_in[6];
    const float* Wo = (const float*)d_in[7];
    float* out = (float*)d_out;

    __half *xqh, *xql, *xkh, *xvh;
    __half *wqh, *wkh, *wvh, *woh;
    __half *qh, *ql, *kh, *vh, *ah, *al;
    cudaGetSymbolAddress((void**)&xqh, g_xqh); cudaGetSymbolAddress((void**)&xql, g_xql);
    cudaGetSymbolAddress((void**)&xkh, g_xkh); cudaGetSymbolAddress((void**)&xvh, g_xvh);
    cudaGetSymbolAddress((void**)&wqh, g_wqh); cudaGetSymbolAddress((void**)&wkh, g_wkh);
    cudaGetSymbolAddress((void**)&wvh, g_wvh); cudaGetSymbolAddress((void**)&woh, g_woh);
    cudaGetSymbolAddress((void**)&qh, g_qh);   cudaGetSymbolAddress((void**)&ql, g_ql);
    cudaGetSymbolAddress((void**)&kh, g_kh);   cudaGetSymbolAddress((void**)&vh, g_vh);
    cudaGetSymbolAddress((void**)&ah, g_ah);   cudaGetSymbolAddress((void**)&al, g_al);

    static int smem_set = 0;
    if (!smem_set) {
        cudaFuncSetAttribute(attn_hmma, cudaFuncAttributeMaxDynamicSharedMemorySize, 2 * AT_BUF);
        smem_set = 1;
    }

    // 1) fused preprocess: split q, convert k/v + weights
    dim3 gprep((M_ * D_ / 4) / 256, 1, 7);
    prep_kernel<<<gprep, 256>>>(q, k, v, Wq, Wk, Wv, Wo);

    // 2) QKV projections: Q -> split pair (2-pass), K/V -> single fp16 (1-pass)
    dim3 gproj(D_ / 128, M_ / 128, 3);
    hmma_gemm3<<<gproj, 256>>>(
        xqh, xql,     wqh, nullptr, qh, ql,
        xkh, nullptr, wkh, nullptr, kh, nullptr,
        xvh, nullptr, wvh, nullptr, vh, nullptr);

    // 3) causal flash attention -> fp16 hi/lo
    dim3 gattn(S_ / 128, B_ * H_);
    attn_hmma<<<gattn, 256, 2 * AT_BUF>>>();

    // 4) output projection (2-pass) -> fp32 d_out
    dim3 gout(D_ / 128, M_ / 128, 1);
    hmma_gemm3<<<gout, 256>>>(
        ah, al, woh, out, nullptr, nullptr,
        ah, al, woh, out, nullptr, nullptr,
        ah, al, woh, out, nullptr, nullptr);
}

// round 7
// speedup vs baseline: 5.6875x; 1.0335x over previous
#include <cuda_runtime.h>
#include <cuda_fp16.h>
#include <cstdint>

#define B_  2
#define S_  2048
#define D_  1024
#define H_  16
#define DK_ 64
#define M_  (B_ * S_)   // 4096

// ---------------------------------------------------------------------------
// Scratch (allocation-free rule: device globals), fp16
// ---------------------------------------------------------------------------
__device__ __half g_xqh[M_ * D_], g_xql[M_ * D_];          // q input split
__device__ __half g_xkh[M_ * D_], g_xvh[M_ * D_];          // k/v input single fp16
__device__ __half g_wqh[D_ * D_], g_wkh[D_ * D_], g_wvh[D_ * D_], g_woh[D_ * D_];
__device__ __half g_qh[M_ * D_], g_ql[M_ * D_];            // projected Q split
__device__ __half g_kh[M_ * D_];                           // projected K fp16
__device__ __half g_vh[M_ * D_];                           // projected V fp16
__device__ __half g_ah[M_ * D_], g_al[M_ * D_];            // attention out split

// ---------------------------------------------------------------------------
__device__ __forceinline__ uint32_t smem_u32(const void* p) {
    uint32_t a;
    asm("{ .reg .u64 t; cvta.to.shared.u64 t, %1; cvt.u32.u64 %0, t; }" : "=r"(a) : "l"(p));
    return a;
}
__device__ __forceinline__ void ldsm_x4(uint32_t* r, uint32_t addr) {
    asm volatile("ldmatrix.sync.aligned.m8n8.x4.shared.b16 {%0,%1,%2,%3}, [%4];"
                 : "=r"(r[0]), "=r"(r[1]), "=r"(r[2]), "=r"(r[3]) : "r"(addr));
}
__device__ __forceinline__ void ldsm_x4_t(uint32_t* r, uint32_t addr) {
    asm volatile("ldmatrix.sync.aligned.m8n8.x4.trans.shared.b16 {%0,%1,%2,%3}, [%4];"
                 : "=r"(r[0]), "=r"(r[1]), "=r"(r[2]), "=r"(r[3]) : "r"(addr));
}
__device__ __forceinline__ void mma_16816(float* c, const uint32_t* a, uint32_t b0, uint32_t b1) {
    asm volatile("mma.sync.aligned.m16n8k16.row.col.f32.f16.f16.f32 "
                 "{%0,%1,%2,%3}, {%4,%5,%6,%7}, {%8,%9}, {%0,%1,%2,%3};"
                 : "+f"(c[0]), "+f"(c[1]), "+f"(c[2]), "+f"(c[3])
                 : "r"(a[0]), "r"(a[1]), "r"(a[2]), "r"(a[3]), "r"(b0), "r"(b1));
}
__device__ __forceinline__ void cp_async16(uint32_t saddr, const void* gaddr) {
    asm volatile("cp.async.cg.shared.global [%0], [%1], 16;" :: "r"(saddr), "l"(gaddr));
}
#define CP_COMMIT()  asm volatile("cp.async.commit_group;" ::: "memory")
#define CP_WAIT(n)   asm volatile("cp.async.wait_group %0;" :: "n"(n) : "memory")
#define SWZ(off) ((off) ^ (((off) >> 3) & 0x70))

__device__ __forceinline__ uint32_t pack_f16x2(float f0, float f1) {
    __half2 h = __floats2half2_rn(f0, f1);
    return *(uint32_t*)&h;
}
__device__ __forceinline__ float f16lo_f(uint32_t p) { return __low2float(*(__half2*)&p); }
__device__ __forceinline__ float f16hi_f(uint32_t p) { return __high2float(*(__half2*)&p); }

// FFMA-pipe 2^x (rel err ~2e-6)
__device__ __forceinline__ float fexp2(float x) {
    x = fmaxf(x, -126.0f);
    float r = rintf(x);
    float f = x - r;
    float p = 1.3333558e-3f;
    p = fmaf(p, f, 9.6181291e-3f);
    p = fmaf(p, f, 5.5504109e-2f);
    p = fmaf(p, f, 2.4022651e-1f);
    p = fmaf(p, f, 6.9314718e-1f);
    p = fmaf(p, f, 1.0f);
    return p * __int_as_float(((int)r + 127) << 23);
}
#define LOG2E 1.4426950408889634f
#define SCALE_C (0.125f * LOG2E)

// ---------------------------------------------------------------------------
// Fused preprocess: z=0 split q; z=1 conv k; z=2 conv v; z=3..6 conv weights.
// ---------------------------------------------------------------------------
__global__ __launch_bounds__(256) void prep_kernel(
    const float* __restrict__ q, const float* __restrict__ k, const float* __restrict__ v,
    const float* __restrict__ Wq, const float* __restrict__ Wk,
    const float* __restrict__ Wv, const float* __restrict__ Wo)
{
    const int z = blockIdx.z;
    const int idx = blockIdx.x * 256 + threadIdx.x;
    const int n4 = (z < 3) ? (M_ * D_ / 4) : (D_ * D_ / 4);
    if (idx >= n4) return;

    const float* src;
    __half* dst;
    switch (z) {
        case 0: src = q;  dst = g_xqh; break;
        case 1: src = k;  dst = g_xkh; break;
        case 2: src = v;  dst = g_xvh; break;
        case 3: src = Wq; dst = g_wqh; break;
        case 4: src = Wk; dst = g_wkh; break;
        case 5: src = Wv; dst = g_wvh; break;
        default: src = Wo; dst = g_woh; break;
    }
    float4 x = ((const float4*)src)[idx];
    uint32_t h0 = pack_f16x2(x.x, x.y);
    uint32_t h1 = pack_f16x2(x.z, x.w);
    ((uint2*)dst)[idx] = make_uint2(h0, h1);
    if (z == 0) {
        uint32_t l0 = pack_f16x2(x.x - f16lo_f(h0), x.y - f16hi_f(h0));
        uint32_t l1 = pack_f16x2(x.z - f16lo_f(h1), x.w - f16hi_f(h1));
        ((uint2*)g_xql)[idx] = make_uint2(l0, l1);
    }
}

// ---------------------------------------------------------------------------
// HMMA GEMM: Y = X @ W^T, fp32 acc. 128x128 CTA, BK=32, 8 warps.
// Fused hi/lo: each stage holds {A_hi, A_lo, B}; one B load serves both passes.
// 3-stage cp.async pipeline, ONE __syncthreads per iteration.
// Epilogue: fp32 (Yf) / fp16 split (Yh,Yl) / fp16 single (Yh).
// ---------------------------------------------------------------------------
#define GSTAGE 24576                 // 3 x 8KB tiles (Ah, Al, B)
#define GSMEM  (3 * GSTAGE)          // 73728
__device__ __forceinline__ uint32_t tile_off(int row, int k) {
    uint32_t b = ((uint32_t)(row >> 1) << 7) | ((uint32_t)(row & 1) << 6) | ((uint32_t)k << 1);
    return SWZ(b);
}

__global__ __launch_bounds__(256, 2) void hmma_gemm3(
    const __half* __restrict__ Xh0, const __half* __restrict__ Xl0, const __half* __restrict__ Wh0,
    float* Yf0, __half* Yh0, __half* Yl0,
    const __half* __restrict__ Xh1, const __half* __restrict__ Xl1, const __half* __restrict__ Wh1,
    float* Yf1, __half* Yh1, __half* Yl1,
    const __half* __restrict__ Xh2, const __half* __restrict__ Xl2, const __half* __restrict__ Wh2,
    float* Yf2, __half* Yh2, __half* Yl2)
{
    const __half *Xh, *Xl, *Wh; float* Yf; __half *Yh, *Yl;
    if (blockIdx.z == 0)      { Xh=Xh0; Xl=Xl0; Wh=Wh0; Yf=Yf0; Yh=Yh0; Yl=Yl0; }
    else if (blockIdx.z == 1) { Xh=Xh1; Xl=Xl1; Wh=Wh1; Yf=Yf1; Yh=Yh1; Yl=Yl1; }
    else                      { Xh=Xh2; Xl=Xl2; Wh=Wh2; Yf=Yf2; Yh=Yh2; Yl=Yl2; }

    extern __shared__ char gsmem[];
    const uint32_t sb = smem_u32(gsmem);

    const int tid = threadIdx.x;
    const int wid = tid >> 5;
    const int lid = tid & 31;
    const int m0 = blockIdx.y * 128;
    const int n0 = blockIdx.x * 128;
    const int wr = (wid & 1) * 64;
    const int wn = (wid >> 1) * 32;

    const int r0 = tid >> 2;
    const int kb = (tid & 3) * 8;
    const uint32_t so0 = tile_off(r0, kb);
    const uint32_t so1 = tile_off(r0 + 64, kb);
    const size_t go0 = (size_t)r0 * D_ + kb;
    const size_t go1 = (size_t)(r0 + 64) * D_ + kb;

    const int sub = lid >> 3, l7 = lid & 7;
    uint32_t offA[2][4], offB[2][2];
#pragma unroll
    for (int ks = 0; ks < 2; ks++) {
#pragma unroll
        for (int i = 0; i < 4; i++)
            offA[ks][i] = tile_off(wr + i * 16 + (sub & 1) * 8 + l7, ks * 16 + (sub >> 1) * 8);
#pragma unroll
        for (int j = 0; j < 2; j++)
            offB[ks][j] = tile_off(wn + j * 16 + (sub >> 1) * 8 + l7, ks * 16 + (sub & 1) * 8);
    }

    float acc[4][4][4];
#pragma unroll
    for (int i = 0; i < 4; i++)
#pragma unroll
        for (int j = 0; j < 4; j++)
#pragma unroll
            for (int c = 0; c < 4; c++) acc[i][j][c] = 0.f;

    auto issue = [&](int it) {
        const int k0 = it * 32;
        const uint32_t st = sb + (uint32_t)(it % 3) * GSTAGE;
        const __half* Ab = Xh + (size_t)m0 * D_ + k0;
        const __half* Bb = Wh + (size_t)n0 * D_ + k0;
        cp_async16(st + so0, Ab + go0);
        cp_async16(st + so1, Ab + go1);
        if (Xl) {
            const __half* Al = Xl + (size_t)m0 * D_ + k0;
            cp_async16(st + 8192 + so0, Al + go0);
            cp_async16(st + 8192 + so1, Al + go1);
        }
        cp_async16(st + 16384 + so0, Bb + go0);
        cp_async16(st + 16384 + so1, Bb + go1);
    };

    issue(0); CP_COMMIT();
    issue(1); CP_COMMIT();

    for (int it = 0; it < 32; it++) {
        if (it < 31) { CP_WAIT(1); } else { CP_WAIT(0); }
        __syncthreads();
        if (it + 2 < 32) { issue(it + 2); CP_COMMIT(); }

        const uint32_t st = sb + (uint32_t)(it % 3) * GSTAGE;
#pragma unroll
        for (int ks = 0; ks < 2; ks++) {
            uint32_t a[4][4], b[2][4];
#pragma unroll
            for (int j = 0; j < 2; j++) ldsm_x4(b[j], st + 16384 + offB[ks][j]);
#pragma unroll
            for (int i = 0; i < 4; i++) ldsm_x4(a[i], st + offA[ks][i]);
#pragma unroll
            for (int i = 0; i < 4; i++)
#pragma unroll
                for (int jj = 0; jj < 4; jj++)
                    mma_16816(acc[i][jj], a[i], b[jj >> 1][(jj & 1) * 2], b[jj >> 1][(jj & 1) * 2 + 1]);
            if (Xl) {
#pragma unroll
                for (int i = 0; i < 4; i++) ldsm_x4(a[i], st + 8192 + offA[ks][i]);
#pragma unroll
                for (int i = 0; i < 4; i++)
#pragma unroll
                    for (int jj = 0; jj < 4; jj++)
                        mma_16816(acc[i][jj], a[i], b[jj >> 1][(jj & 1) * 2], b[jj >> 1][(jj & 1) * 2 + 1]);
            }
        }
    }

    const int er = lid >> 2;
    const int ec = (lid & 3) * 2;
#pragma unroll
    for (int i = 0; i < 4; i++)
#pragma unroll
        for (int jj = 0; jj < 4; jj++) {
            size_t p0 = (size_t)(m0 + wr + i * 16 + er) * D_ + n0 + wn + jj * 8 + ec;
            size_t p1 = p0 + 8 * (size_t)D_;
            float* a4 = acc[i][jj];
            if (Yl) {
                uint32_t h0 = pack_f16x2(a4[0], a4[1]);
                uint32_t h1 = pack_f16x2(a4[2], a4[3]);
                uint32_t l0 = pack_f16x2(a4[0] - f16lo_f(h0), a4[1] - f16hi_f(h0));
                uint32_t l1 = pack_f16x2(a4[2] - f16lo_f(h1), a4[3] - f16hi_f(h1));
                *(uint32_t*)(Yh + p0) = h0; *(uint32_t*)(Yl + p0) = l0;
                *(uint32_t*)(Yh + p1) = h1; *(uint32_t*)(Yl + p1) = l1;
            } else if (Yh) {
                *(uint32_t*)(Yh + p0) = pack_f16x2(a4[0], a4[1]);
                *(uint32_t*)(Yh + p1) = pack_f16x2(a4[2], a4[3]);
            } else {
                *(float2*)(Yf + p0) = make_float2(a4[0], a4[1]);
                *(float2*)(Yf + p1) = make_float2(a4[2], a4[3]);
            }
        }
}

// ---------------------------------------------------------------------------
// HMMA causal flash attention, fp16. 3-stage K/V pipeline, one sync per tile.
// QK: (Qh + Ql) . K (2 passes).  PV: Ph . V (1 pass).
// ---------------------------------------------------------------------------
#define ASTAGE 16384   // K(8KB) + V(8KB)
__global__ __launch_bounds__(256, 1) void attn_hmma()
{
    __shared__ char asmem[3 * ASTAGE];      // 48KB static
    const uint32_t sb = smem_u32(asmem);
    const int tid = threadIdx.x, wid = tid >> 5, lid = tid & 31;
    const int qt = (int)gridDim.x - 1 - (int)blockIdx.x;   // heavy tiles first
    const int bh = blockIdx.y;
    const int b = bh >> 4, h = bh & 15;
    const int sub = lid >> 3, l7 = lid & 7;
    const int quad = lid >> 2, qlane = lid & 3;

    const int qrow = qt * 128 + wid * 16 + quad;

    uint32_t Qh[4][4], Ql[4][4];
    {
        const size_t base = (size_t)(b * S_ + qrow) * D_ + h * DK_ + qlane * 2;
        const size_t b8 = base + 8 * (size_t)D_;
#pragma unroll
        for (int ks = 0; ks < 4; ks++) {
            int cc = ks * 16;
            Qh[ks][0] = *(const uint32_t*)(g_qh + base + cc);
            Qh[ks][1] = *(const uint32_t*)(g_qh + b8 + cc);
            Qh[ks][2] = *(const uint32_t*)(g_qh + base + cc + 8);
            Qh[ks][3] = *(const uint32_t*)(g_qh + b8 + cc + 8);
            Ql[ks][0] = *(const uint32_t*)(g_ql + base + cc);
            Ql[ks][1] = *(const uint32_t*)(g_ql + b8 + cc);
            Ql[ks][2] = *(const uint32_t*)(g_ql + base + cc + 8);
            Ql[ks][3] = *(const uint32_t*)(g_ql + b8 + cc + 8);
        }
    }

    float O[8][4];
#pragma unroll
    for (int j = 0; j < 8; j++)
#pragma unroll
        for (int c = 0; c < 4; c++) O[j][c] = 0.f;
    float m0 = -1e30f, m1 = -1e30f, l0 = 0.f, l1 = 0.f;

    const size_t hoff = (size_t)(b * S_) * D_ + h * DK_;
    const __half* gK = g_kh + hoff;
    const __half* gV = g_vh + hoff;

    const int crow = tid >> 3;
    const int cc16 = tid & 7;

    auto issue = [&](int kt) {
        const uint32_t bufb = sb + (uint32_t)(kt % 3) * ASTAGE;
#pragma unroll
        for (int t = 0; t < 4; t++) {
            const int tensor = t >> 1;                 // 0=K, 1=V
            const int row = (t & 1) * 32 + crow;
            const __half* gp = tensor ? gV : gK;
            cp_async16(bufb + (uint32_t)tensor * 8192 + SWZ((uint32_t)(row * 128 + cc16 * 16)),
                       gp + (size_t)(kt * 64 + row) * D_ + cc16 * 8);
        }
    };

    const int ntiles = 2 * qt + 2;
    issue(0); CP_COMMIT();
    if (ntiles > 1) { issue(1); CP_COMMIT(); }

    for (int kt = 0; kt < ntiles; kt++) {
        if (kt < ntiles - 1) { CP_WAIT(1); } else { CP_WAIT(0); }
        __syncthreads();
        if (kt + 2 < ntiles) { issue(kt + 2); CP_COMMIT(); }

        const uint32_t bufb = sb + (uint32_t)(kt % 3) * ASTAGE;
        const uint32_t sK = bufb, sV = bufb + 8192;
        const int kg0 = kt * 64;

        // ---- scores = (Qh + Ql) . K^T ----
        float sc[8][4];
#pragma unroll
        for (int j = 0; j < 8; j++)
#pragma unroll
            for (int c = 0; c < 4; c++) sc[j][c] = 0.f;

#pragma unroll
        for (int ks = 0; ks < 4; ks++) {
            uint32_t bK[4][4];
#pragma unroll
            for (int j = 0; j < 4; j++)
                ldsm_x4(bK[j], sK + SWZ((uint32_t)((j * 16 + (sub >> 1) * 8 + l7) * 128
                                                  + (ks * 16 + (sub & 1) * 8) * 2)));
#pragma unroll
            for (int j = 0; j < 4; j++) {
                mma_16816(sc[2 * j],     Qh[ks], bK[j][0], bK[j][1]);
                mma_16816(sc[2 * j + 1], Qh[ks], bK[j][2], bK[j][3]);
                mma_16816(sc[2 * j],     Ql[ks], bK[j][0], bK[j][1]);
                mma_16816(sc[2 * j + 1], Ql[ks], bK[j][2], bK[j][3]);
            }
        }

#pragma unroll
        for (int j = 0; j < 8; j++)
#pragma unroll
            for (int c = 0; c < 4; c++) sc[j][c] *= SCALE_C;
        if (kt >= 2 * qt) {
#pragma unroll
            for (int j = 0; j < 8; j++)
#pragma unroll
                for (int c = 0; c < 4; c++) {
                    int kc = kg0 + j * 8 + qlane * 2 + (c & 1);
                    int qr = qrow + ((c >= 2) ? 8 : 0);
                    if (kc > qr) sc[j][c] = -1e30f;
                }
        }

        // ---- online softmax (log2 domain) ----
        float t0 = -1e30f, t1 = -1e30f;
#pragma unroll
        for (int j = 0; j < 8; j++) {
            t0 = fmaxf(t0, fmaxf(sc[j][0], sc[j][1]));
            t1 = fmaxf(t1, fmaxf(sc[j][2], sc[j][3]));
        }
        t0 = fmaxf(t0, __shfl_xor_sync(0xffffffffu, t0, 1));
        t0 = fmaxf(t0, __shfl_xor_sync(0xffffffffu, t0, 2));
        t1 = fmaxf(t1, __shfl_xor_sync(0xffffffffu, t1, 1));
        t1 = fmaxf(t1, __shfl_xor_sync(0xffffffffu, t1, 2));
        float m0n = fmaxf(m0, t0), m1n = fmaxf(m1, t1);
        float cr0 = fexp2(m0 - m0n), cr1 = fexp2(m1 - m1n);
        m0 = m0n; m1 = m1n;

        float s0 = 0.f, s1 = 0.f;
#pragma unroll
        for (int j = 0; j < 8; j++) {
            sc[j][0] = fexp2(sc[j][0] - m0);
            sc[j][1] = fexp2(sc[j][1] - m0);
            sc[j][2] = fexp2(sc[j][2] - m1);
            sc[j][3] = fexp2(sc[j][3] - m1);
            s0 += sc[j][0] + sc[j][1];
            s1 += sc[j][2] + sc[j][3];
        }
        s0 += __shfl_xor_sync(0xffffffffu, s0, 1);
        s0 += __shfl_xor_sync(0xffffffffu, s0, 2);
        s1 += __shfl_xor_sync(0xffffffffu, s1, 1);
        s1 += __shfl_xor_sync(0xffffffffu, s1, 2);
        l0 = l0 * cr0 + s0;
        l1 = l1 * cr1 + s1;
#pragma unroll
        for (int j = 0; j < 8; j++) {
            O[j][0] *= cr0; O[j][1] *= cr0; O[j][2] *= cr1; O[j][3] *= cr1;
        }

        // ---- pack P (fp16) as A fragments ----
        uint32_t Ph[4][4];
#pragma unroll
        for (int ks = 0; ks < 4; ks++) {
            float* e0 = sc[2 * ks];
            float* e1 = sc[2 * ks + 1];
            Ph[ks][0] = pack_f16x2(e0[0], e0[1]);
            Ph[ks][1] = pack_f16x2(e0[2], e0[3]);
            Ph[ks][2] = pack_f16x2(e1[0], e1[1]);
            Ph[ks][3] = pack_f16x2(e1[2], e1[3]);
        }

        // ---- O += Ph . V ----
#pragma unroll
        for (int ks = 0; ks < 4; ks++) {
            uint32_t bV[4][4];
#pragma unroll
            for (int j = 0; j < 4; j++)
                ldsm_x4_t(bV[j], sV + SWZ((uint32_t)((ks * 16 + (sub & 1) * 8 + l7) * 128
                                                    + (j * 16 + (sub >> 1) * 8) * 2)));
#pragma unroll
            for (int j = 0; j < 4; j++) {
                mma_16816(O[2 * j],     Ph[ks], bV[j][0], bV[j][1]);
                mma_16816(O[2 * j + 1], Ph[ks], bV[j][2], bV[j][3]);
            }
        }
    }

    // ---- epilogue: normalize, split to fp16 hi/lo ----
    const float i0 = 1.f / l0, i1 = 1.f / l1;
    const size_t ob = (size_t)(b * S_ + qrow) * D_ + h * DK_ + qlane * 2;
    const size_t ob8 = ob + 8 * (size_t)D_;
#pragma unroll
    for (int j = 0; j < 8; j++) {
        float v0 = O[j][0] * i0, v1 = O[j][1] * i0;
        float v2 = O[j][2] * i1, v3 = O[j][3] * i1;
        uint32_t h0 = pack_f16x2(v0, v1);
        uint32_t h1 = pack_f16x2(v2, v3);
        uint32_t lo0 = pack_f16x2(v0 - f16lo_f(h0), v1 - f16hi_f(h0));
        uint32_t lo1 = pack_f16x2(v2 - f16lo_f(h1), v3 - f16hi_f(h1));
        *(uint32_t*)(g_ah + ob + j * 8)  = h0;
        *(uint32_t*)(g_al + ob + j * 8)  = lo0;
        *(uint32_t*)(g_ah + ob8 + j * 8) = h1;
        *(uint32_t*)(g_al + ob8 + j * 8) = lo1;
    }
}

// ---------------------------------------------------------------------------
extern "C" void kernel_launch(void* const* d_in, const int* in_sizes, int n_in,
                              void* d_out, int out_size)
{
    (void)in_sizes; (void)n_in; (void)out_size;
    const float* q  = (const float*)d_in[0];
    const float* k  = (const float*)d_in[1];
    const float* v  = (const float*)d_in[2];
    const float* Wq = (const float*)d_in[4];
    const float* Wk = (const float*)d_in[5];
    const float* Wv = (const float*)d_in[6];
    const float* Wo = (const float*)d_in[7];
    float* out = (float*)d_out;

    __half *xqh, *xql, *xkh, *xvh;
    __half *wqh, *wkh, *wvh, *woh;
    __half *qh, *ql, *kh, *vh, *ah, *al;
    cudaGetSymbolAddress((void**)&xqh, g_xqh); cudaGetSymbolAddress((void**)&xql, g_xql);
    cudaGetSymbolAddress((void**)&xkh, g_xkh); cudaGetSymbolAddress((void**)&xvh, g_xvh);
    cudaGetSymbolAddress((void**)&wqh, g_wqh); cudaGetSymbolAddress((void**)&wkh, g_wkh);
    cudaGetSymbolAddress((void**)&wvh, g_wvh); cudaGetSymbolAddress((void**)&woh, g_woh);
    cudaGetSymbolAddress((void**)&qh, g_qh);   cudaGetSymbolAddress((void**)&ql, g_ql);
    cudaGetSymbolAddress((void**)&kh, g_kh);   cudaGetSymbolAddress((void**)&vh, g_vh);
    cudaGetSymbolAddress((void**)&ah, g_ah);   cudaGetSymbolAddress((void**)&al, g_al);

    static int smem_set = 0;
    if (!smem_set) {
        cudaFuncSetAttribute(hmma_gemm3, cudaFuncAttributeMaxDynamicSharedMemorySize, GSMEM);
        smem_set = 1;
    }

    // 1) fused preprocess
    dim3 gprep((M_ * D_ / 4) / 256, 1, 7);
    prep_kernel<<<gprep, 256>>>(q, k, v, Wq, Wk, Wv, Wo);

    // 2) QKV projections: Q -> split pair (fused 2-pass), K/V -> single fp16
    dim3 gproj(D_ / 128, M_ / 128, 3);
    hmma_gemm3<<<gproj, 256, GSMEM>>>(
        xqh, xql,     wqh, nullptr, qh, ql,
        xkh, nullptr, wkh, nullptr, kh, nullptr,
        xvh, nullptr, wvh, nullptr, vh, nullptr);

    // 3) causal flash attention -> fp16 hi/lo
    dim3 gattn(S_ / 128, B_ * H_);
    attn_hmma<<<gattn, 256>>>();

    // 4) output projection (fused 2-pass) -> fp32 d_out
    dim3 gout(D_ / 128, M_ / 128, 1);
    hmma_gemm3<<<gout, 256, GSMEM>>>(
        ah, al, woh, out, nullptr, nullptr,
        ah, al, woh, out, nullptr, nullptr,
        ah, al, woh, out, nullptr, nullptr);
}